// round 9
// baseline (speedup 1.0000x reference)
#include <cuda_runtime.h>

// ---------------- problem constants ----------------
#define BB   32
#define TT   256
#define SS   9
#define EE   631
#define DD   512
#define FFD  512
#define HH   8
#define HDD  64
#define LL   2
#define OUTD 512
#define NSEQ (BB*TT)          // 8192 sequences
#define NTOK (NSEQ*SS)        // 73728 tokens
#define EPS  1e-5f

typedef unsigned long long ull;

// ---------------- scratch (static device globals; no allocs) ----------------
__device__ float g_h[(size_t)NTOK * DD];        // hidden state      (151 MB)
__device__ float g_qkv[(size_t)NTOK * 3 * DD];  // qkv / sublayer y  (453 MB)
__device__ float g_tmp[(size_t)NTOK * DD];      // ctx / ff hidden   (151 MB)
__device__ float g_raw[(size_t)NSEQ * OUTD];    // raw_emb
__device__ float g_ov[(size_t)NSEQ * OUTD];     // fc output

// ---------------- f32x2 helpers ----------------
__device__ __forceinline__ ull dup2(float v) {
    ull d; unsigned u = __float_as_uint(v);
    asm("mov.b64 %0, {%1, %1};" : "=l"(d) : "r"(u));
    return d;
}
__device__ __forceinline__ void ffma2(ull &c, ull a, ull b) {
    asm("fma.rn.f32x2 %0, %1, %2, %0;" : "+l"(c) : "l"(a), "l"(b));
}
union F2 { ull u; float2 f; };

// ---------------- GEMM: C[M,N] = act(A[M,K] @ W[K,N] + bias) ----------------
// BM=128 BN=64 BK=16, 256 threads, 8x4 per thread, f32x2 (pairs along M).
// All dims are multiples of tile sizes for this problem (no bounds checks).
template<int ACT>
__global__ __launch_bounds__(256)
void gemm_kernel(const float* __restrict__ A, int lda,
                 const float* __restrict__ W, int ldw,
                 const float* __restrict__ bias,
                 float* __restrict__ C, int ldc, int K)
{
    const int BM = 128, BN = 64, BK = 16;
    __shared__ float  As[BK][BM + 4];   // stride 132: conflict-free transpose stores
    __shared__ float4 Bs[BK][BN / 4];

    const int bx  = blockIdx.x, by = blockIdx.y;
    const int tid = threadIdx.x;
    const int tx  = tid & 15;           // n-direction (4 cols)
    const int ty  = tid >> 4;           // m-direction (8 rows)

    ull acc[4][4];
#pragma unroll
    for (int p = 0; p < 4; p++)
#pragma unroll
        for (int n = 0; n < 4; n++) acc[p][n] = 0ull;

    const float* Abase = A + (size_t)by * BM * lda;
    const float* Wbase = W + (size_t)bx * BN;

    for (int k0 = 0; k0 < K; k0 += BK) {
        __syncthreads();
        // load A tile 128x16 (512 float4), transpose into As[k][m]
#pragma unroll
        for (int i = 0; i < 2; i++) {
            int u  = tid + i * 256;
            int r  = u >> 2, c4 = u & 3;
            float4 v = *reinterpret_cast<const float4*>(Abase + (size_t)r * lda + k0 + c4 * 4);
            As[c4 * 4 + 0][r] = v.x;
            As[c4 * 4 + 1][r] = v.y;
            As[c4 * 4 + 2][r] = v.z;
            As[c4 * 4 + 3][r] = v.w;
        }
        // load B tile 16x64 (256 float4)
        {
            int kr = tid >> 4, c4 = tid & 15;
            Bs[kr][c4] = *reinterpret_cast<const float4*>(Wbase + (size_t)(k0 + kr) * ldw + c4 * 4);
        }
        __syncthreads();

#pragma unroll
        for (int kk = 0; kk < BK; kk++) {
            const ull* a2 = reinterpret_cast<const ull*>(&As[kk][ty * 8]);  // 8B aligned
            ull a[4];
#pragma unroll
            for (int p = 0; p < 4; p++) a[p] = a2[p];
            float4 b4 = Bs[kk][tx];
            ull bd[4] = { dup2(b4.x), dup2(b4.y), dup2(b4.z), dup2(b4.w) };
#pragma unroll
            for (int p = 0; p < 4; p++)
#pragma unroll
                for (int n = 0; n < 4; n++)
                    ffma2(acc[p][n], a[p], bd[n]);
        }
    }

    // epilogue: bias (+relu), vectorized stores
    const int col = bx * BN + tx * 4;
    float4 bias4 = *reinterpret_cast<const float4*>(bias + col);
#pragma unroll
    for (int p = 0; p < 4; p++) {
        float lo[4], hi[4];
#pragma unroll
        for (int n = 0; n < 4; n++) {
            F2 t; t.u = acc[p][n];
            lo[n] = t.f.x; hi[n] = t.f.y;
        }
        float4 o0 = make_float4(lo[0] + bias4.x, lo[1] + bias4.y, lo[2] + bias4.z, lo[3] + bias4.w);
        float4 o1 = make_float4(hi[0] + bias4.x, hi[1] + bias4.y, hi[2] + bias4.z, hi[3] + bias4.w);
        if (ACT == 1) {
            o0.x = fmaxf(o0.x, 0.f); o0.y = fmaxf(o0.y, 0.f); o0.z = fmaxf(o0.z, 0.f); o0.w = fmaxf(o0.w, 0.f);
            o1.x = fmaxf(o1.x, 0.f); o1.y = fmaxf(o1.y, 0.f); o1.z = fmaxf(o1.z, 0.f); o1.w = fmaxf(o1.w, 0.f);
        }
        size_t row0 = (size_t)by * BM + ty * 8 + 2 * p;
        *reinterpret_cast<float4*>(C + row0 * ldc + col)       = o0;
        *reinterpret_cast<float4*>(C + (row0 + 1) * ldc + col) = o1;
    }
}

// ---------------- embedding gather: h[i,:] = adapt_w[x[i]] + adapt_b ----------------
__global__ void embed_kernel(const int* __restrict__ x,
                             const float* __restrict__ w,
                             const float* __restrict__ b,
                             float* __restrict__ h)
{
    int i = blockIdx.x, t = threadIdx.x;      // 73728 blocks x 128 threads
    int e = x[i];
    float4 wv = reinterpret_cast<const float4*>(w)[(size_t)e * 128 + t];
    float4 bv = reinterpret_cast<const float4*>(b)[t];
    reinterpret_cast<float4*>(h)[(size_t)i * 128 + t] =
        make_float4(wv.x + bv.x, wv.y + bv.y, wv.z + bv.z, wv.w + bv.w);
}

// ---------------- raw_emb: raw[n,:] = sum_s adapt2_w[s*E + x[n,s]] + adapt2_b ----------------
__global__ void raw_kernel(const int* __restrict__ x,
                           const float* __restrict__ w2,
                           const float* __restrict__ b2,
                           float* __restrict__ raw)
{
    int n = blockIdx.x, t = threadIdx.x;      // 8192 blocks x 128 threads
    __shared__ int xs[SS];
    if (t < SS) xs[t] = x[n * SS + t];
    __syncthreads();
    float4 acc = reinterpret_cast<const float4*>(b2)[t];
#pragma unroll
    for (int s = 0; s < SS; s++) {
        float4 v = reinterpret_cast<const float4*>(w2)[((size_t)s * EE + xs[s]) * 128 + t];
        acc.x += v.x; acc.y += v.y; acc.z += v.z; acc.w += v.w;
    }
    reinterpret_cast<float4*>(raw)[(size_t)n * 128 + t] = acc;
}

// ---------------- attention: one CTA per sequence ----------------
#define ROWP 516   // padded SMEM row stride (floats): breaks k/v bank conflicts
#define ATTN_SMEM ((3 * SS * ROWP + HH * SS * SS) * 4)

__global__ __launch_bounds__(256)
void attn_kernel(const float* __restrict__ qkv, float* __restrict__ ctx)
{
    extern __shared__ float sm[];
    float* sq = sm;
    float* sk = sq + SS * ROWP;
    float* sv = sk + SS * ROWP;
    float* sc = sv + SS * ROWP;               // [h*81 + i*9 + j]

    const int n = blockIdx.x, tid = threadIdx.x;

    // stage q/k/v (9 x 1536 floats = 3456 float4)
    const float4* qkv4 = reinterpret_cast<const float4*>(qkv + (size_t)n * SS * 1536);
    for (int u = tid; u < 3456; u += 256) {
        int s = u / 384, c4 = u % 384;
        float4 v = qkv4[s * 384 + c4];
        float* dst;
        if (c4 < 128)       dst = sq + s * ROWP + c4 * 4;
        else if (c4 < 256)  dst = sk + s * ROWP + (c4 - 128) * 4;
        else                dst = sv + s * ROWP + (c4 - 256) * 4;
        *reinterpret_cast<float4*>(dst) = v;
    }
    __syncthreads();

    // scores[h][i][j] = q_i,h . k_j,h / 8
    for (int p = tid; p < HH * SS * SS; p += 256) {
        int h = p / (SS * SS), rem = p % (SS * SS), i = rem / SS, j = rem % SS;
        const float* qp = sq + i * ROWP + h * HDD;
        const float* kp = sk + j * ROWP + h * HDD;
        float dot = 0.f;
#pragma unroll
        for (int d = 0; d < HDD; d++) dot += qp[d] * kp[d];
        sc[p] = dot * 0.125f;
    }
    __syncthreads();

    // softmax over j (72 rows of 9)
    if (tid < HH * SS) {
        float* row = sc + tid * SS;
        float m = row[0];
#pragma unroll
        for (int j = 1; j < SS; j++) m = fmaxf(m, row[j]);
        float s2 = 0.f;
#pragma unroll
        for (int j = 0; j < SS; j++) { float e = __expf(row[j] - m); row[j] = e; s2 += e; }
        float inv = 1.f / s2;
#pragma unroll
        for (int j = 0; j < SS; j++) row[j] *= inv;
    }
    __syncthreads();

    // ctx[i][h*64+d] = sum_j attn[h][i][j] * v[j][h*64+d]   (1152 float4)
    float4* ctx4 = reinterpret_cast<float4*>(ctx + (size_t)n * SS * DD);
    for (int u = tid; u < SS * 128; u += 256) {
        int i = u >> 7, c4 = u & 127;
        int h = c4 >> 4;
        const float* arow = sc + (h * SS + i) * SS;
        float4 acc = make_float4(0.f, 0.f, 0.f, 0.f);
#pragma unroll
        for (int j = 0; j < SS; j++) {
            float a = arow[j];
            float4 vv = *reinterpret_cast<const float4*>(sv + j * ROWP + c4 * 4);
            acc.x += a * vv.x; acc.y += a * vv.y; acc.z += a * vv.z; acc.w += a * vv.w;
        }
        ctx4[i * 128 + c4] = acc;
    }
}

// ---------------- fused residual + layernorm: h = LN(h + y)*g + b ----------------
__global__ __launch_bounds__(256)
void add_ln_kernel(float* __restrict__ h, const float* __restrict__ y,
                   const float* __restrict__ gamma, const float* __restrict__ beta)
{
    int warp = threadIdx.x >> 5, lane = threadIdx.x & 31;
    size_t row = (size_t)blockIdx.x * 8 + warp;
    float4* h4       = reinterpret_cast<float4*>(h) + row * 128;
    const float4* y4 = reinterpret_cast<const float4*>(y) + row * 128;

    float4 xv[4];
    float sum = 0.f, sq = 0.f;
#pragma unroll
    for (int q = 0; q < 4; q++) {
        float4 a = h4[q * 32 + lane], b = y4[q * 32 + lane];
        float4 v = make_float4(a.x + b.x, a.y + b.y, a.z + b.z, a.w + b.w);
        xv[q] = v;
        sum += v.x + v.y + v.z + v.w;
        sq  += v.x * v.x + v.y * v.y + v.z * v.z + v.w * v.w;
    }
#pragma unroll
    for (int o = 16; o > 0; o >>= 1) {
        sum += __shfl_xor_sync(0xffffffffu, sum, o);
        sq  += __shfl_xor_sync(0xffffffffu, sq,  o);
    }
    float mean = sum * (1.f / 512.f);
    float var  = sq * (1.f / 512.f) - mean * mean;
    float rstd = rsqrtf(var + EPS);

    const float4* g4 = reinterpret_cast<const float4*>(gamma);
    const float4* b4 = reinterpret_cast<const float4*>(beta);
#pragma unroll
    for (int q = 0; q < 4; q++) {
        float4 g = g4[q * 32 + lane], bb = b4[q * 32 + lane], v = xv[q];
        float4 o;
        o.x = (v.x - mean) * rstd * g.x + bb.x;
        o.y = (v.y - mean) * rstd * g.y + bb.y;
        o.z = (v.z - mean) * rstd * g.z + bb.z;
        o.w = (v.w - mean) * rstd * g.w + bb.w;
        h4[q * 32 + lane] = o;
    }
}

// ---------------- final: out = raw * (1 + relu(ov)) ----------------
__global__ void final_kernel(const float* __restrict__ raw,
                             const float* __restrict__ ov,
                             float* __restrict__ out)
{
    int i = blockIdx.x * blockDim.x + threadIdx.x;   // float4 index
    float4 r = reinterpret_cast<const float4*>(raw)[i];
    float4 o = reinterpret_cast<const float4*>(ov)[i];
    float4 res;
    res.x = r.x * (1.f + fmaxf(o.x, 0.f));
    res.y = r.y * (1.f + fmaxf(o.y, 0.f));
    res.z = r.z * (1.f + fmaxf(o.z, 0.f));
    res.w = r.w * (1.f + fmaxf(o.w, 0.f));
    reinterpret_cast<float4*>(out)[i] = res;
}

// ---------------- launch ----------------
extern "C" void kernel_launch(void* const* d_in, const int* in_sizes, int n_in,
                              void* d_out, int out_size)
{
    const int*   x        = (const int*)  d_in[0];
    const float* adapt2_w = (const float*)d_in[1];
    const float* adapt2_b = (const float*)d_in[2];
    const float* adapt_w  = (const float*)d_in[3];
    const float* adapt_b  = (const float*)d_in[4];
    const float* qkv_w    = (const float*)d_in[5];
    const float* qkv_b    = (const float*)d_in[6];
    const float* out_w    = (const float*)d_in[7];
    const float* out_b    = (const float*)d_in[8];
    const float* ln1_g    = (const float*)d_in[9];
    const float* ln1_b    = (const float*)d_in[10];
    const float* lin1_w   = (const float*)d_in[11];
    const float* lin1_b   = (const float*)d_in[12];
    const float* lin2_w   = (const float*)d_in[13];
    const float* lin2_b   = (const float*)d_in[14];
    const float* ln2_g    = (const float*)d_in[15];
    const float* ln2_b    = (const float*)d_in[16];
    const float* fc_w     = (const float*)d_in[17];
    const float* fc_b     = (const float*)d_in[18];
    float* out = (float*)d_out;

    float *h, *qkvb, *tmp, *raw, *ov;
    cudaGetSymbolAddress((void**)&h,    g_h);
    cudaGetSymbolAddress((void**)&qkvb, g_qkv);
    cudaGetSymbolAddress((void**)&tmp,  g_tmp);
    cudaGetSymbolAddress((void**)&raw,  g_raw);
    cudaGetSymbolAddress((void**)&ov,   g_ov);

    cudaFuncSetAttribute(attn_kernel, cudaFuncAttributeMaxDynamicSharedMemorySize, ATTN_SMEM);

    embed_kernel<<<NTOK, 128>>>(x, adapt_w, adapt_b, h);
    raw_kernel<<<NSEQ, 128>>>(x, adapt2_w, adapt2_b, raw);

    for (int l = 0; l < LL; l++) {
        const float* qw  = qkv_w  + (size_t)l * DD * 3 * DD;
        const float* qb  = qkv_b  + (size_t)l * 3 * DD;
        const float* ow  = out_w  + (size_t)l * DD * DD;
        const float* ob  = out_b  + (size_t)l * DD;
        const float* l1w = lin1_w + (size_t)l * DD * FFD;
        const float* l1b = lin1_b + (size_t)l * FFD;
        const float* l2w = lin2_w + (size_t)l * FFD * DD;
        const float* l2b = lin2_b + (size_t)l * DD;

        // qkv = h @ qkv_w + b     (73728 x 1536)
        gemm_kernel<0><<<dim3(1536 / 64, NTOK / 128), 256>>>(h, DD, qw, 3 * DD, qb, qkvb, 3 * DD, DD);
        // ctx (g_tmp)
        attn_kernel<<<NSEQ, 256, ATTN_SMEM>>>(qkvb, tmp);
        // y = ctx @ out_w + b    (reuse g_qkv as 512-wide y)
        gemm_kernel<0><<<dim3(DD / 64, NTOK / 128), 256>>>(tmp, DD, ow, DD, ob, qkvb, DD, DD);
        // h = LN(h + y)
        add_ln_kernel<<<NTOK / 8, 256>>>(h, qkvb, ln1_g + (size_t)l * DD, ln1_b + (size_t)l * DD);
        // t = relu(h @ lin1 + b)
        gemm_kernel<1><<<dim3(FFD / 64, NTOK / 128), 256>>>(h, DD, l1w, FFD, l1b, tmp, FFD, DD);
        // y = t @ lin2 + b
        gemm_kernel<0><<<dim3(DD / 64, NTOK / 128), 256>>>(tmp, FFD, l2w, DD, l2b, qkvb, DD, FFD);
        // h = LN(h + y)
        add_ln_kernel<<<NTOK / 8, 256>>>(h, qkvb, ln2_g + (size_t)l * DD, ln2_b + (size_t)l * DD);
    }

    // ov = cls @ fc_w + fc_b  (cls rows are h[n*9], so lda = 9*512)
    gemm_kernel<0><<<dim3(OUTD / 64, NSEQ / 128), 256>>>(h, SS * DD, fc_w, OUTD, fc_b, ov, OUTD, DD);

    // out = raw * (1 + relu(ov))
    final_kernel<<<(NSEQ * OUTD / 4) / 256, 256>>>(raw, ov, out);
}

// round 13
// speedup vs baseline: 3.8972x; 3.8972x over previous
#include <cuda_runtime.h>
#include <cuda_fp16.h>
#include <cstdint>

// ---------------- problem constants ----------------
#define BB   32
#define TT   256
#define SS   9
#define EE   631
#define DD   512
#define FFD  512
#define HH   8
#define HDD  64
#define LL   2
#define OUTD 512
#define NSEQ (BB*TT)          // 8192 sequences
#define NTOK (NSEQ*SS)        // 73728 tokens
#define EPS  1e-5f

// ---------------- scratch (static device globals; no allocs) ----------------
__device__ float  g_h[(size_t)NTOK * DD];          // hidden state fp32
__device__ __half g_h16[(size_t)NTOK * DD];        // fp16 shadow of h
__device__ __half g_qkv16[(size_t)NTOK * 3 * DD];  // qkv (fp16)
__device__ __half g_ctx16[(size_t)NTOK * DD];      // attention ctx (fp16)
__device__ __half g_ff16[(size_t)NTOK * DD];       // relu(lin1) (fp16)
__device__ __half g_y16[(size_t)NTOK * DD];        // sublayer output y (fp16)
__device__ float  g_raw[(size_t)NSEQ * OUTD];      // raw_emb
__device__ float  g_ov[(size_t)NSEQ * OUTD];       // fc output
__device__ __half g_wT16[3407872];                 // transposed weights [N,K] fp16

// weight-transpose offsets (elements)
#define WT_QKV(l)  ((size_t)(l) * 786432)
#define WT_OUT(l)  (1572864 + (size_t)(l) * 262144)
#define WT_LIN1(l) (2097152 + (size_t)(l) * 262144)
#define WT_LIN2(l) (2621440 + (size_t)(l) * 262144)
#define WT_FC      (3145728)

// ---------------- PTX helpers (all target-neutral, sm_80-era) ----------------
__device__ __forceinline__ unsigned smem_u32(const void* p) {
    unsigned a;
    asm("{ .reg .u64 t; cvta.to.shared.u64 t, %1; cvt.u32.u64 %0, t; }" : "=r"(a) : "l"(p));
    return a;
}
__device__ __forceinline__ void cp16(unsigned dst, const void* src) {
    asm volatile("cp.async.cg.shared.global [%0], [%1], 16;" :: "r"(dst), "l"(src) : "memory");
}
__device__ __forceinline__ void ldmx4(unsigned addr, unsigned &r0, unsigned &r1,
                                      unsigned &r2, unsigned &r3) {
    asm volatile("ldmatrix.sync.aligned.m8n8.x4.shared.b16 {%0,%1,%2,%3}, [%4];"
                 : "=r"(r0), "=r"(r1), "=r"(r2), "=r"(r3) : "r"(addr));
}
__device__ __forceinline__ void mma_f16(float& d0, float& d1, float& d2, float& d3,
                                        unsigned a0, unsigned a1, unsigned a2, unsigned a3,
                                        unsigned b0, unsigned b1) {
    asm volatile("mma.sync.aligned.m16n8k16.row.col.f32.f16.f16.f32 "
                 "{%0,%1,%2,%3}, {%4,%5,%6,%7}, {%8,%9}, {%0,%1,%2,%3};"
                 : "+f"(d0), "+f"(d1), "+f"(d2), "+f"(d3)
                 : "r"(a0), "r"(a1), "r"(a2), "r"(a3), "r"(b0), "r"(b1));
}

// ---------------- fp16 mma GEMM ----------------
// C[M,N] = act(A[M,K=512] @ BT[N,K=512]^T + bias)
// BM=128 BN=128 BK=32, 256 threads (8 warps, 4x2, warp tile 32x64),
// 4-stage cp.async pipeline, ldmatrix from 80B-padded SMEM rows.
#define ST_A_BYTES (128 * 80)            // 10240
#define ST_BYTES   (2 * ST_A_BYTES)      // 20480 per stage
#define GEMM_SMEM  (4 * ST_BYTES)        // 81920

__device__ __forceinline__ void gemm_issue(unsigned st,
                                           const __half* __restrict__ A0, int lda,
                                           const __half* __restrict__ B0, int k0)
{
    const int tid = threadIdx.x;
#pragma unroll
    for (int i = 0; i < 2; i++) {
        int c = tid + i * 256;
        int row = c >> 2, seg = c & 3;
        cp16(st + row * 80 + seg * 16,              A0 + (size_t)row * lda + k0 + seg * 8);
        cp16(st + ST_A_BYTES + row * 80 + seg * 16, B0 + (size_t)row * 512 + k0 + seg * 8);
    }
    asm volatile("cp.async.commit_group;" ::: "memory");
}

template<int ACT, int OUT16>
__global__ __launch_bounds__(256)
void gemm_mma(const __half* __restrict__ A, int lda,
              const __half* __restrict__ BT,
              const float* __restrict__ bias,
              void* __restrict__ Cv, int ldc)
{
    extern __shared__ char smem[];
    const unsigned sbase = smem_u32(smem);
    const int tid = threadIdx.x, lid = tid & 31, wid = tid >> 5;
    const int wm = wid & 3, wn = wid >> 2;      // 4 x 2 warp grid
    const int bx = blockIdx.x, by = blockIdx.y;

    const __half* Ab = A  + (size_t)by * 128 * lda;
    const __half* Bb = BT + (size_t)bx * 128 * 512;

    gemm_issue(sbase,                Ab, lda, Bb, 0);
    gemm_issue(sbase + ST_BYTES,     Ab, lda, Bb, 32);
    gemm_issue(sbase + 2 * ST_BYTES, Ab, lda, Bb, 64);

    float c[2][8][4];
#pragma unroll
    for (int i = 0; i < 2; i++)
#pragma unroll
        for (int j = 0; j < 8; j++)
#pragma unroll
            for (int q = 0; q < 4; q++) c[i][j][q] = 0.f;

    // per-lane ldmatrix offsets
    const unsigned a_row = lid & 15, a_k = (lid >> 4) * 8;
    const unsigned b_n = (lid & 7) + ((lid >> 4) << 3), b_k = ((lid >> 3) & 1) * 8;

#pragma unroll 1
    for (int k = 0; k < 16; k++) {
        asm volatile("cp.async.wait_group 2;" ::: "memory");
        __syncthreads();
        const unsigned sA = sbase + (k & 3) * ST_BYTES;
        const unsigned sB = sA + ST_A_BYTES;
#pragma unroll
        for (int ks = 0; ks < 2; ks++) {
            unsigned a[2][4], b[4][4];
#pragma unroll
            for (int i = 0; i < 2; i++)
                ldmx4(sA + (wm * 32 + i * 16 + a_row) * 80 + (ks * 16 + a_k) * 2,
                      a[i][0], a[i][1], a[i][2], a[i][3]);
#pragma unroll
            for (int jj = 0; jj < 4; jj++)
                ldmx4(sB + (wn * 64 + jj * 16 + b_n) * 80 + (ks * 16 + b_k) * 2,
                      b[jj][0], b[jj][1], b[jj][2], b[jj][3]);
#pragma unroll
            for (int i = 0; i < 2; i++)
#pragma unroll
                for (int j = 0; j < 8; j++)
                    mma_f16(c[i][j][0], c[i][j][1], c[i][j][2], c[i][j][3],
                            a[i][0], a[i][1], a[i][2], a[i][3],
                            b[j >> 1][(j & 1) * 2], b[j >> 1][(j & 1) * 2 + 1]);
        }
        if (k < 13) gemm_issue(sbase + ((k + 3) & 3) * ST_BYTES, Ab, lda, Bb, (k + 3) * 32);
        else        asm volatile("cp.async.commit_group;" ::: "memory");  // keep group count uniform
    }

    // ---------------- epilogue ----------------
    const int qrow = lid >> 2, qcol = (lid & 3) * 2;
    const int gcol = bx * 128 + wn * 64 + qcol;
    float2 bv[8];
#pragma unroll
    for (int j = 0; j < 8; j++) bv[j] = *reinterpret_cast<const float2*>(bias + gcol + j * 8);

    const size_t rbase = (size_t)by * 128 + wm * 32 + qrow;
#pragma unroll
    for (int i = 0; i < 2; i++) {
#pragma unroll
        for (int hh = 0; hh < 2; hh++) {
            size_t row = rbase + i * 16 + hh * 8;
#pragma unroll
            for (int j = 0; j < 8; j++) {
                float x = c[i][j][hh * 2 + 0] + bv[j].x;
                float y = c[i][j][hh * 2 + 1] + bv[j].y;
                if (ACT) { x = fmaxf(x, 0.f); y = fmaxf(y, 0.f); }
                if (OUT16) {
                    __half* p = (__half*)Cv + row * ldc + gcol + j * 8;
                    *reinterpret_cast<__half2*>(p) = __floats2half2_rn(x, y);
                } else {
                    float* p = (float*)Cv + row * ldc + gcol + j * 8;
                    *reinterpret_cast<float2*>(p) = make_float2(x, y);
                }
            }
        }
    }
}

// ---------------- weight transpose+convert: in[K,N] fp32 -> out[N,K] fp16 ----------------
__global__ void transpose_kernel(const float* __restrict__ in, __half* __restrict__ out,
                                 int K, int N)
{
    __shared__ float t[32][33];
    int n0 = blockIdx.x * 32, k0 = blockIdx.y * 32;
    int x = threadIdx.x, y = threadIdx.y;     // 32 x 8
#pragma unroll
    for (int i = 0; i < 32; i += 8)
        t[y + i][x] = in[(size_t)(k0 + y + i) * N + n0 + x];
    __syncthreads();
#pragma unroll
    for (int i = 0; i < 32; i += 8)
        out[(size_t)(n0 + y + i) * K + k0 + x] = __float2half_rn(t[x][y + i]);
}

// ---------------- embedding gather ----------------
__global__ void embed_kernel(const int* __restrict__ x,
                             const float* __restrict__ w,
                             const float* __restrict__ b,
                             float* __restrict__ h, __half* __restrict__ h16)
{
    int i = blockIdx.x, t = threadIdx.x;     // NTOK blocks x 128 threads
    int e = x[i];
    float4 wv = reinterpret_cast<const float4*>(w)[(size_t)e * 128 + t];
    float4 bv = reinterpret_cast<const float4*>(b)[t];
    float4 r = make_float4(wv.x + bv.x, wv.y + bv.y, wv.z + bv.z, wv.w + bv.w);
    reinterpret_cast<float4*>(h)[(size_t)i * 128 + t] = r;
    __half2* hp = reinterpret_cast<__half2*>(h16 + (size_t)i * 512 + t * 4);
    hp[0] = __floats2half2_rn(r.x, r.y);
    hp[1] = __floats2half2_rn(r.z, r.w);
}

// ---------------- raw_emb ----------------
__global__ void raw_kernel(const int* __restrict__ x,
                           const float* __restrict__ w2,
                           const float* __restrict__ b2,
                           float* __restrict__ raw)
{
    int n = blockIdx.x, t = threadIdx.x;
    __shared__ int xs[SS];
    if (t < SS) xs[t] = x[n * SS + t];
    __syncthreads();
    float4 acc = reinterpret_cast<const float4*>(b2)[t];
#pragma unroll
    for (int s = 0; s < SS; s++) {
        float4 v = reinterpret_cast<const float4*>(w2)[((size_t)s * EE + xs[s]) * 128 + t];
        acc.x += v.x; acc.y += v.y; acc.z += v.z; acc.w += v.w;
    }
    reinterpret_cast<float4*>(raw)[(size_t)n * 128 + t] = acc;
}

// ---------------- attention: one CTA per sequence (fp16 in, fp32 math, fp16 out) ----------------
#define ROWP 516
#define ATTN_SMEM ((3 * SS * ROWP + HH * SS * SS) * 4)

__global__ __launch_bounds__(256)
void attn_kernel(const __half* __restrict__ qkv16, __half* __restrict__ ctx16)
{
    extern __shared__ float sm[];
    float* sq = sm;
    float* sk = sq + SS * ROWP;
    float* sv = sk + SS * ROWP;
    float* sc = sv + SS * ROWP;

    const int n = blockIdx.x, tid = threadIdx.x;

    // stage q/k/v: 9 x 1536 halves = 1728 x 8-half chunks
    const uint4* q16 = reinterpret_cast<const uint4*>(qkv16 + (size_t)n * SS * 1536);
    for (int u = tid; u < SS * 192; u += 256) {
        int s = u / 192, c8 = u % 192;
        uint4 rawv = q16[u];
        const __half2* hp = reinterpret_cast<const __half2*>(&rawv);
        float2 f0 = __half22float2(hp[0]), f1 = __half22float2(hp[1]);
        float2 f2 = __half22float2(hp[2]), f3 = __half22float2(hp[3]);
        int col = c8 * 8;
        float* dst;
        if (col < 512)       dst = sq + s * ROWP + col;
        else if (col < 1024) dst = sk + s * ROWP + (col - 512);
        else                 dst = sv + s * ROWP + (col - 1024);
        reinterpret_cast<float4*>(dst)[0] = make_float4(f0.x, f0.y, f1.x, f1.y);
        reinterpret_cast<float4*>(dst)[1] = make_float4(f2.x, f2.y, f3.x, f3.y);
    }
    __syncthreads();

    for (int p = tid; p < HH * SS * SS; p += 256) {
        int h = p / (SS * SS), rem = p % (SS * SS), i = rem / SS, j = rem % SS;
        const float* qp = sq + i * ROWP + h * HDD;
        const float* kp = sk + j * ROWP + h * HDD;
        float dot = 0.f;
#pragma unroll
        for (int d = 0; d < HDD; d++) dot += qp[d] * kp[d];
        sc[p] = dot * 0.125f;
    }
    __syncthreads();

    if (tid < HH * SS) {
        float* row = sc + tid * SS;
        float m = row[0];
#pragma unroll
        for (int j = 1; j < SS; j++) m = fmaxf(m, row[j]);
        float s2 = 0.f;
#pragma unroll
        for (int j = 0; j < SS; j++) { float e = __expf(row[j] - m); row[j] = e; s2 += e; }
        float inv = 1.f / s2;
#pragma unroll
        for (int j = 0; j < SS; j++) row[j] *= inv;
    }
    __syncthreads();

    __half* c16 = ctx16 + (size_t)n * SS * DD;
    for (int u = tid; u < SS * 128; u += 256) {
        int i = u >> 7, c4 = u & 127;
        int h = c4 >> 4;
        const float* arow = sc + (h * SS + i) * SS;
        float4 acc = make_float4(0.f, 0.f, 0.f, 0.f);
#pragma unroll
        for (int j = 0; j < SS; j++) {
            float a = arow[j];
            float4 vv = *reinterpret_cast<const float4*>(sv + j * ROWP + c4 * 4);
            acc.x += a * vv.x; acc.y += a * vv.y; acc.z += a * vv.z; acc.w += a * vv.w;
        }
        __half2* cp2 = reinterpret_cast<__half2*>(c16 + i * 512 + c4 * 4);
        cp2[0] = __floats2half2_rn(acc.x, acc.y);
        cp2[1] = __floats2half2_rn(acc.z, acc.w);
    }
}

// ---------------- fused residual + layernorm: h = LN(h + y16)*g + b  (+ fp16 shadow) ----------------
__global__ __launch_bounds__(256)
void add_ln_kernel(float* __restrict__ h, __half* __restrict__ h16,
                   const __half* __restrict__ y16,
                   const float* __restrict__ gamma, const float* __restrict__ beta)
{
    int warp = threadIdx.x >> 5, lane = threadIdx.x & 31;
    size_t row = (size_t)blockIdx.x * 8 + warp;
    float4* h4        = reinterpret_cast<float4*>(h) + row * 128;
    const __half2* y2 = reinterpret_cast<const __half2*>(y16) + row * 256;

    float4 xv[4];
    float sum = 0.f, sq = 0.f;
#pragma unroll
    for (int q = 0; q < 4; q++) {
        float4 a = h4[q * 32 + lane];
        __half2 ya = y2[(q * 32 + lane) * 2], yb = y2[(q * 32 + lane) * 2 + 1];
        float2 fa = __half22float2(ya), fb = __half22float2(yb);
        float4 v = make_float4(a.x + fa.x, a.y + fa.y, a.z + fb.x, a.w + fb.y);
        xv[q] = v;
        sum += v.x + v.y + v.z + v.w;
        sq  += v.x * v.x + v.y * v.y + v.z * v.z + v.w * v.w;
    }
#pragma unroll
    for (int o = 16; o > 0; o >>= 1) {
        sum += __shfl_xor_sync(0xffffffffu, sum, o);
        sq  += __shfl_xor_sync(0xffffffffu, sq,  o);
    }
    float mean = sum * (1.f / 512.f);
    float var  = sq * (1.f / 512.f) - mean * mean;
    float rstd = rsqrtf(var + EPS);

    const float4* g4 = reinterpret_cast<const float4*>(gamma);
    const float4* b4 = reinterpret_cast<const float4*>(beta);
    __half2* hp = reinterpret_cast<__half2*>(h16) + row * 256;
#pragma unroll
    for (int q = 0; q < 4; q++) {
        float4 g = g4[q * 32 + lane], bb = b4[q * 32 + lane], v = xv[q];
        float4 o;
        o.x = (v.x - mean) * rstd * g.x + bb.x;
        o.y = (v.y - mean) * rstd * g.y + bb.y;
        o.z = (v.z - mean) * rstd * g.z + bb.z;
        o.w = (v.w - mean) * rstd * g.w + bb.w;
        h4[q * 32 + lane] = o;
        hp[(q * 32 + lane) * 2]     = __floats2half2_rn(o.x, o.y);
        hp[(q * 32 + lane) * 2 + 1] = __floats2half2_rn(o.z, o.w);
    }
}

// ---------------- final: out = raw * (1 + relu(ov)) ----------------
__global__ void final_kernel(const float* __restrict__ raw,
                             const float* __restrict__ ov,
                             float* __restrict__ out)
{
    int i = blockIdx.x * blockDim.x + threadIdx.x;
    float4 r = reinterpret_cast<const float4*>(raw)[i];
    float4 o = reinterpret_cast<const float4*>(ov)[i];
    float4 res;
    res.x = r.x * (1.f + fmaxf(o.x, 0.f));
    res.y = r.y * (1.f + fmaxf(o.y, 0.f));
    res.z = r.z * (1.f + fmaxf(o.z, 0.f));
    res.w = r.w * (1.f + fmaxf(o.w, 0.f));
    reinterpret_cast<float4*>(out)[i] = res;
}

// ---------------- launch ----------------
extern "C" void kernel_launch(void* const* d_in, const int* in_sizes, int n_in,
                              void* d_out, int out_size)
{
    const int*   x        = (const int*)  d_in[0];
    const float* adapt2_w = (const float*)d_in[1];
    const float* adapt2_b = (const float*)d_in[2];
    const float* adapt_w  = (const float*)d_in[3];
    const float* adapt_b  = (const float*)d_in[4];
    const float* qkv_w    = (const float*)d_in[5];
    const float* qkv_b    = (const float*)d_in[6];
    const float* out_w    = (const float*)d_in[7];
    const float* out_b    = (const float*)d_in[8];
    const float* ln1_g    = (const float*)d_in[9];
    const float* ln1_b    = (const float*)d_in[10];
    const float* lin1_w   = (const float*)d_in[11];
    const float* lin1_b   = (const float*)d_in[12];
    const float* lin2_w   = (const float*)d_in[13];
    const float* lin2_b   = (const float*)d_in[14];
    const float* ln2_g    = (const float*)d_in[15];
    const float* ln2_b    = (const float*)d_in[16];
    const float* fc_w     = (const float*)d_in[17];
    const float* fc_b     = (const float*)d_in[18];
    float* out = (float*)d_out;

    float  *h, *raw, *ov;
    __half *h16, *qkv16, *ctx16, *ff16, *y16, *wT16;
    cudaGetSymbolAddress((void**)&h,     g_h);
    cudaGetSymbolAddress((void**)&h16,   g_h16);
    cudaGetSymbolAddress((void**)&qkv16, g_qkv16);
    cudaGetSymbolAddress((void**)&ctx16, g_ctx16);
    cudaGetSymbolAddress((void**)&ff16,  g_ff16);
    cudaGetSymbolAddress((void**)&y16,   g_y16);
    cudaGetSymbolAddress((void**)&raw,   g_raw);
    cudaGetSymbolAddress((void**)&ov,    g_ov);
    cudaGetSymbolAddress((void**)&wT16,  g_wT16);

    cudaFuncSetAttribute(attn_kernel,    cudaFuncAttributeMaxDynamicSharedMemorySize, ATTN_SMEM);
    cudaFuncSetAttribute(gemm_mma<0, 0>, cudaFuncAttributeMaxDynamicSharedMemorySize, GEMM_SMEM);
    cudaFuncSetAttribute(gemm_mma<0, 1>, cudaFuncAttributeMaxDynamicSharedMemorySize, GEMM_SMEM);
    cudaFuncSetAttribute(gemm_mma<1, 1>, cudaFuncAttributeMaxDynamicSharedMemorySize, GEMM_SMEM);

    // transpose + fp16-convert all weights to [N, K]
    dim3 tb(32, 8);
    for (int l = 0; l < LL; l++) {
        transpose_kernel<<<dim3(1536 / 32, 512 / 32), tb>>>(qkv_w  + (size_t)l * DD * 3 * DD, wT16 + WT_QKV(l),  512, 1536);
        transpose_kernel<<<dim3(512 / 32,  512 / 32), tb>>>(out_w  + (size_t)l * DD * DD,     wT16 + WT_OUT(l),  512, 512);
        transpose_kernel<<<dim3(512 / 32,  512 / 32), tb>>>(lin1_w + (size_t)l * DD * FFD,    wT16 + WT_LIN1(l), 512, 512);
        transpose_kernel<<<dim3(512 / 32,  512 / 32), tb>>>(lin2_w + (size_t)l * FFD * DD,    wT16 + WT_LIN2(l), 512, 512);
    }
    transpose_kernel<<<dim3(512 / 32, 512 / 32), tb>>>(fc_w, wT16 + WT_FC, 512, 512);

    embed_kernel<<<NTOK, 128>>>(x, adapt_w, adapt_b, h, h16);
    raw_kernel<<<NSEQ, 128>>>(x, adapt2_w, adapt2_b, raw);

    for (int l = 0; l < LL; l++) {
        const float* qb  = qkv_b  + (size_t)l * 3 * DD;
        const float* ob  = out_b  + (size_t)l * DD;
        const float* l1b = lin1_b + (size_t)l * FFD;
        const float* l2b = lin2_b + (size_t)l * DD;

        // qkv = h @ qkv_w + b   -> fp16 (73728 x 1536)
        gemm_mma<0, 1><<<dim3(1536 / 128, NTOK / 128), 256, GEMM_SMEM>>>(h16, 512, wT16 + WT_QKV(l), qb, qkv16, 3 * DD);
        // ctx (fp16)
        attn_kernel<<<NSEQ, 256, ATTN_SMEM>>>(qkv16, ctx16);
        // y = ctx @ out_w + b   -> fp16
        gemm_mma<0, 1><<<dim3(DD / 128, NTOK / 128), 256, GEMM_SMEM>>>(ctx16, 512, wT16 + WT_OUT(l), ob, y16, DD);
        // h = LN(h + y)
        add_ln_kernel<<<NTOK / 8, 256>>>(h, h16, y16, ln1_g + (size_t)l * DD, ln1_b + (size_t)l * DD);
        // t = relu(h @ lin1 + b) -> fp16
        gemm_mma<1, 1><<<dim3(FFD / 128, NTOK / 128), 256, GEMM_SMEM>>>(h16, 512, wT16 + WT_LIN1(l), l1b, ff16, FFD);
        // y = t @ lin2 + b -> fp16
        gemm_mma<0, 1><<<dim3(DD / 128, NTOK / 128), 256, GEMM_SMEM>>>(ff16, 512, wT16 + WT_LIN2(l), l2b, y16, DD);
        // h = LN(h + y)
        add_ln_kernel<<<NTOK / 8, 256>>>(h, h16, y16, ln2_g + (size_t)l * DD, ln2_b + (size_t)l * DD);
    }

    // ov = cls @ fc_w + fc_b  (cls rows are h16[n*9,:], so lda = 9*512) -> fp32
    gemm_mma<0, 0><<<dim3(OUTD / 128, NSEQ / 128), 256, GEMM_SMEM>>>(h16, SS * DD, wT16 + WT_FC, fc_b, ov, OUTD);

    // out = raw * (1 + relu(ov))
    final_kernel<<<(NSEQ * OUTD / 4) / 256, 256>>>(raw, ov, out);
}

// round 14
// speedup vs baseline: 3.9018x; 1.0012x over previous
#include <cuda_runtime.h>
#include <cuda_fp16.h>
#include <cstdint>

// ---------------- problem constants ----------------
#define BB   32
#define TT   256
#define SS   9
#define EE   631
#define DD   512
#define FFD  512
#define HH   8
#define HDD  64
#define LL   2
#define OUTD 512
#define NSEQ (BB*TT)          // 8192 sequences
#define NTOK (NSEQ*SS)        // 73728 tokens
#define EPS  1e-5f

// ---------------- scratch (static device globals; no allocs) ----------------
__device__ float  g_h[(size_t)NTOK * DD];          // hidden state fp32
__device__ __half g_h16[(size_t)NTOK * DD];        // fp16 shadow of h
__device__ __half g_qkv16[(size_t)NTOK * 3 * DD];  // qkv (fp16)
__device__ __half g_ctx16[(size_t)NTOK * DD];      // attention ctx (fp16)
__device__ __half g_ff16[(size_t)NTOK * DD];       // relu(lin1) (fp16)
__device__ __half g_y16[(size_t)NTOK * DD];        // sublayer output y (fp16)
__device__ float  g_raw[(size_t)NSEQ * OUTD];      // raw_emb
__device__ float  g_ov[(size_t)NSEQ * OUTD];       // fc output
__device__ __half g_wT16[3407872];                 // transposed weights [N,K] fp16

// weight-transpose offsets (elements)
#define WT_QKV(l)  ((size_t)(l) * 786432)
#define WT_OUT(l)  (1572864 + (size_t)(l) * 262144)
#define WT_LIN1(l) (2097152 + (size_t)(l) * 262144)
#define WT_LIN2(l) (2621440 + (size_t)(l) * 262144)
#define WT_FC      (3145728)

// ---------------- PTX helpers (all target-neutral, sm_80-era) ----------------
__device__ __forceinline__ unsigned smem_u32(const void* p) {
    unsigned a;
    asm("{ .reg .u64 t; cvta.to.shared.u64 t, %1; cvt.u32.u64 %0, t; }" : "=r"(a) : "l"(p));
    return a;
}
__device__ __forceinline__ void cp16(unsigned dst, const void* src) {
    asm volatile("cp.async.cg.shared.global [%0], [%1], 16;" :: "r"(dst), "l"(src) : "memory");
}
__device__ __forceinline__ void ldmx4(unsigned addr, unsigned &r0, unsigned &r1,
                                      unsigned &r2, unsigned &r3) {
    asm volatile("ldmatrix.sync.aligned.m8n8.x4.shared.b16 {%0,%1,%2,%3}, [%4];"
                 : "=r"(r0), "=r"(r1), "=r"(r2), "=r"(r3) : "r"(addr));
}
__device__ __forceinline__ void mma_f16(float& d0, float& d1, float& d2, float& d3,
                                        unsigned a0, unsigned a1, unsigned a2, unsigned a3,
                                        unsigned b0, unsigned b1) {
    asm volatile("mma.sync.aligned.m16n8k16.row.col.f32.f16.f16.f32 "
                 "{%0,%1,%2,%3}, {%4,%5,%6,%7}, {%8,%9}, {%0,%1,%2,%3};"
                 : "+f"(d0), "+f"(d1), "+f"(d2), "+f"(d3)
                 : "r"(a0), "r"(a1), "r"(a2), "r"(a3), "r"(b0), "r"(b1));
}

// ---------------- fp16 mma GEMM ----------------
// C[M,N] = act(A[M,K=512] @ BT[N,K=512]^T + bias)
// BM=128 BN=128 BK=32, 256 threads (8 warps, 4x2, warp tile 32x64),
// 4-stage cp.async pipeline, ldmatrix from 80B-padded SMEM rows.
#define ST_A_BYTES (128 * 80)            // 10240
#define ST_BYTES   (2 * ST_A_BYTES)      // 20480 per stage
#define GEMM_SMEM  (4 * ST_BYTES)        // 81920

__device__ __forceinline__ void gemm_issue(unsigned st,
                                           const __half* __restrict__ A0, int lda,
                                           const __half* __restrict__ B0, int k0)
{
    const int tid = threadIdx.x;
#pragma unroll
    for (int i = 0; i < 2; i++) {
        int c = tid + i * 256;
        int row = c >> 2, seg = c & 3;
        cp16(st + row * 80 + seg * 16,              A0 + (size_t)row * lda + k0 + seg * 8);
        cp16(st + ST_A_BYTES + row * 80 + seg * 16, B0 + (size_t)row * 512 + k0 + seg * 8);
    }
    asm volatile("cp.async.commit_group;" ::: "memory");
}

template<int ACT, int OUT16>
__global__ __launch_bounds__(256)
void gemm_mma(const __half* __restrict__ A, int lda,
              const __half* __restrict__ BT,
              const float* __restrict__ bias,
              void* __restrict__ Cv, int ldc)
{
    extern __shared__ char smem[];
    const unsigned sbase = smem_u32(smem);
    const int tid = threadIdx.x, lid = tid & 31, wid = tid >> 5;
    const int wm = wid & 3, wn = wid >> 2;      // 4 x 2 warp grid
    const int bx = blockIdx.x, by = blockIdx.y;

    const __half* Ab = A  + (size_t)by * 128 * lda;
    const __half* Bb = BT + (size_t)bx * 128 * 512;

    gemm_issue(sbase,                Ab, lda, Bb, 0);
    gemm_issue(sbase + ST_BYTES,     Ab, lda, Bb, 32);
    gemm_issue(sbase + 2 * ST_BYTES, Ab, lda, Bb, 64);

    float c[2][8][4];
#pragma unroll
    for (int i = 0; i < 2; i++)
#pragma unroll
        for (int j = 0; j < 8; j++)
#pragma unroll
            for (int q = 0; q < 4; q++) c[i][j][q] = 0.f;

    // per-lane ldmatrix offsets
    const unsigned a_row = lid & 15, a_k = (lid >> 4) * 8;
    const unsigned b_n = (lid & 7) + ((lid >> 4) << 3), b_k = ((lid >> 3) & 1) * 8;

#pragma unroll 1
    for (int k = 0; k < 16; k++) {
        asm volatile("cp.async.wait_group 2;" ::: "memory");
        __syncthreads();
        const unsigned sA = sbase + (k & 3) * ST_BYTES;
        const unsigned sB = sA + ST_A_BYTES;
#pragma unroll
        for (int ks = 0; ks < 2; ks++) {
            unsigned a[2][4], b[4][4];
#pragma unroll
            for (int i = 0; i < 2; i++)
                ldmx4(sA + (wm * 32 + i * 16 + a_row) * 80 + (ks * 16 + a_k) * 2,
                      a[i][0], a[i][1], a[i][2], a[i][3]);
#pragma unroll
            for (int jj = 0; jj < 4; jj++)
                ldmx4(sB + (wn * 64 + jj * 16 + b_n) * 80 + (ks * 16 + b_k) * 2,
                      b[jj][0], b[jj][1], b[jj][2], b[jj][3]);
#pragma unroll
            for (int i = 0; i < 2; i++)
#pragma unroll
                for (int j = 0; j < 8; j++)
                    mma_f16(c[i][j][0], c[i][j][1], c[i][j][2], c[i][j][3],
                            a[i][0], a[i][1], a[i][2], a[i][3],
                            b[j >> 1][(j & 1) * 2], b[j >> 1][(j & 1) * 2 + 1]);
        }
        if (k < 13) gemm_issue(sbase + ((k + 3) & 3) * ST_BYTES, Ab, lda, Bb, (k + 3) * 32);
        else        asm volatile("cp.async.commit_group;" ::: "memory");  // keep group count uniform
    }

    // ---------------- epilogue ----------------
    const int qrow = lid >> 2, qcol = (lid & 3) * 2;
    const int gcol = bx * 128 + wn * 64 + qcol;
    float2 bv[8];
#pragma unroll
    for (int j = 0; j < 8; j++) bv[j] = *reinterpret_cast<const float2*>(bias + gcol + j * 8);

    const size_t rbase = (size_t)by * 128 + wm * 32 + qrow;
#pragma unroll
    for (int i = 0; i < 2; i++) {
#pragma unroll
        for (int hh = 0; hh < 2; hh++) {
            size_t row = rbase + i * 16 + hh * 8;
#pragma unroll
            for (int j = 0; j < 8; j++) {
                float x = c[i][j][hh * 2 + 0] + bv[j].x;
                float y = c[i][j][hh * 2 + 1] + bv[j].y;
                if (ACT) { x = fmaxf(x, 0.f); y = fmaxf(y, 0.f); }
                if (OUT16) {
                    __half* p = (__half*)Cv + row * ldc + gcol + j * 8;
                    *reinterpret_cast<__half2*>(p) = __floats2half2_rn(x, y);
                } else {
                    float* p = (float*)Cv + row * ldc + gcol + j * 8;
                    *reinterpret_cast<float2*>(p) = make_float2(x, y);
                }
            }
        }
    }
}

// ---------------- weight transpose+convert: in[K,N] fp32 -> out[N,K] fp16 ----------------
__global__ void transpose_kernel(const float* __restrict__ in, __half* __restrict__ out,
                                 int K, int N)
{
    __shared__ float t[32][33];
    int n0 = blockIdx.x * 32, k0 = blockIdx.y * 32;
    int x = threadIdx.x, y = threadIdx.y;     // 32 x 8
#pragma unroll
    for (int i = 0; i < 32; i += 8)
        t[y + i][x] = in[(size_t)(k0 + y + i) * N + n0 + x];
    __syncthreads();
#pragma unroll
    for (int i = 0; i < 32; i += 8)
        out[(size_t)(n0 + y + i) * K + k0 + x] = __float2half_rn(t[x][y + i]);
}

// ---------------- embedding gather ----------------
__global__ void embed_kernel(const int* __restrict__ x,
                             const float* __restrict__ w,
                             const float* __restrict__ b,
                             float* __restrict__ h, __half* __restrict__ h16)
{
    int i = blockIdx.x, t = threadIdx.x;     // NTOK blocks x 128 threads
    int e = x[i];
    float4 wv = reinterpret_cast<const float4*>(w)[(size_t)e * 128 + t];
    float4 bv = reinterpret_cast<const float4*>(b)[t];
    float4 r = make_float4(wv.x + bv.x, wv.y + bv.y, wv.z + bv.z, wv.w + bv.w);
    reinterpret_cast<float4*>(h)[(size_t)i * 128 + t] = r;
    __half2* hp = reinterpret_cast<__half2*>(h16 + (size_t)i * 512 + t * 4);
    hp[0] = __floats2half2_rn(r.x, r.y);
    hp[1] = __floats2half2_rn(r.z, r.w);
}

// ---------------- raw_emb ----------------
__global__ void raw_kernel(const int* __restrict__ x,
                           const float* __restrict__ w2,
                           const float* __restrict__ b2,
                           float* __restrict__ raw)
{
    int n = blockIdx.x, t = threadIdx.x;
    __shared__ int xs[SS];
    if (t < SS) xs[t] = x[n * SS + t];
    __syncthreads();
    float4 acc = reinterpret_cast<const float4*>(b2)[t];
#pragma unroll
    for (int s = 0; s < SS; s++) {
        float4 v = reinterpret_cast<const float4*>(w2)[((size_t)s * EE + xs[s]) * 128 + t];
        acc.x += v.x; acc.y += v.y; acc.z += v.z; acc.w += v.w;
    }
    reinterpret_cast<float4*>(raw)[(size_t)n * 128 + t] = acc;
}

// ---------------- attention: one CTA per sequence (fp16 in, fp32 math, fp16 out) ----------------
#define ROWP 516
#define ATTN_SMEM ((3 * SS * ROWP + HH * SS * SS) * 4)

__global__ __launch_bounds__(256)
void attn_kernel(const __half* __restrict__ qkv16, __half* __restrict__ ctx16)
{
    extern __shared__ float sm[];
    float* sq = sm;
    float* sk = sq + SS * ROWP;
    float* sv = sk + SS * ROWP;
    float* sc = sv + SS * ROWP;

    const int n = blockIdx.x, tid = threadIdx.x;

    // stage q/k/v: 9 x 1536 halves = 1728 x 8-half chunks
    const uint4* q16 = reinterpret_cast<const uint4*>(qkv16 + (size_t)n * SS * 1536);
    for (int u = tid; u < SS * 192; u += 256) {
        int s = u / 192, c8 = u % 192;
        uint4 rawv = q16[u];
        const __half2* hp = reinterpret_cast<const __half2*>(&rawv);
        float2 f0 = __half22float2(hp[0]), f1 = __half22float2(hp[1]);
        float2 f2 = __half22float2(hp[2]), f3 = __half22float2(hp[3]);
        int col = c8 * 8;
        float* dst;
        if (col < 512)       dst = sq + s * ROWP + col;
        else if (col < 1024) dst = sk + s * ROWP + (col - 512);
        else                 dst = sv + s * ROWP + (col - 1024);
        reinterpret_cast<float4*>(dst)[0] = make_float4(f0.x, f0.y, f1.x, f1.y);
        reinterpret_cast<float4*>(dst)[1] = make_float4(f2.x, f2.y, f3.x, f3.y);
    }
    __syncthreads();

    for (int p = tid; p < HH * SS * SS; p += 256) {
        int h = p / (SS * SS), rem = p % (SS * SS), i = rem / SS, j = rem % SS;
        const float* qp = sq + i * ROWP + h * HDD;
        const float* kp = sk + j * ROWP + h * HDD;
        float dot = 0.f;
#pragma unroll
        for (int d = 0; d < HDD; d++) dot += qp[d] * kp[d];
        sc[p] = dot * 0.125f;
    }
    __syncthreads();

    if (tid < HH * SS) {
        float* row = sc + tid * SS;
        float m = row[0];
#pragma unroll
        for (int j = 1; j < SS; j++) m = fmaxf(m, row[j]);
        float s2 = 0.f;
#pragma unroll
        for (int j = 0; j < SS; j++) { float e = __expf(row[j] - m); row[j] = e; s2 += e; }
        float inv = 1.f / s2;
#pragma unroll
        for (int j = 0; j < SS; j++) row[j] *= inv;
    }
    __syncthreads();

    __half* c16 = ctx16 + (size_t)n * SS * DD;
    for (int u = tid; u < SS * 128; u += 256) {
        int i = u >> 7, c4 = u & 127;
        int h = c4 >> 4;
        const float* arow = sc + (h * SS + i) * SS;
        float4 acc = make_float4(0.f, 0.f, 0.f, 0.f);
#pragma unroll
        for (int j = 0; j < SS; j++) {
            float a = arow[j];
            float4 vv = *reinterpret_cast<const float4*>(sv + j * ROWP + c4 * 4);
            acc.x += a * vv.x; acc.y += a * vv.y; acc.z += a * vv.z; acc.w += a * vv.w;
        }
        __half2* cp2 = reinterpret_cast<__half2*>(c16 + i * 512 + c4 * 4);
        cp2[0] = __floats2half2_rn(acc.x, acc.y);
        cp2[1] = __floats2half2_rn(acc.z, acc.w);
    }
}

// ---------------- fused residual + layernorm: h = LN(h + y16)*g + b  (+ fp16 shadow) ----------------
__global__ __launch_bounds__(256)
void add_ln_kernel(float* __restrict__ h, __half* __restrict__ h16,
                   const __half* __restrict__ y16,
                   const float* __restrict__ gamma, const float* __restrict__ beta)
{
    int warp = threadIdx.x >> 5, lane = threadIdx.x & 31;
    size_t row = (size_t)blockIdx.x * 8 + warp;
    float4* h4        = reinterpret_cast<float4*>(h) + row * 128;
    const __half2* y2 = reinterpret_cast<const __half2*>(y16) + row * 256;

    float4 xv[4];
    float sum = 0.f, sq = 0.f;
#pragma unroll
    for (int q = 0; q < 4; q++) {
        float4 a = h4[q * 32 + lane];
        __half2 ya = y2[(q * 32 + lane) * 2], yb = y2[(q * 32 + lane) * 2 + 1];
        float2 fa = __half22float2(ya), fb = __half22float2(yb);
        float4 v = make_float4(a.x + fa.x, a.y + fa.y, a.z + fb.x, a.w + fb.y);
        xv[q] = v;
        sum += v.x + v.y + v.z + v.w;
        sq  += v.x * v.x + v.y * v.y + v.z * v.z + v.w * v.w;
    }
#pragma unroll
    for (int o = 16; o > 0; o >>= 1) {
        sum += __shfl_xor_sync(0xffffffffu, sum, o);
        sq  += __shfl_xor_sync(0xffffffffu, sq,  o);
    }
    float mean = sum * (1.f / 512.f);
    float var  = sq * (1.f / 512.f) - mean * mean;
    float rstd = rsqrtf(var + EPS);

    const float4* g4 = reinterpret_cast<const float4*>(gamma);
    const float4* b4 = reinterpret_cast<const float4*>(beta);
    __half2* hp = reinterpret_cast<__half2*>(h16) + row * 256;
#pragma unroll
    for (int q = 0; q < 4; q++) {
        float4 g = g4[q * 32 + lane], bb = b4[q * 32 + lane], v = xv[q];
        float4 o;
        o.x = (v.x - mean) * rstd * g.x + bb.x;
        o.y = (v.y - mean) * rstd * g.y + bb.y;
        o.z = (v.z - mean) * rstd * g.z + bb.z;
        o.w = (v.w - mean) * rstd * g.w + bb.w;
        h4[q * 32 + lane] = o;
        hp[(q * 32 + lane) * 2]     = __floats2half2_rn(o.x, o.y);
        hp[(q * 32 + lane) * 2 + 1] = __floats2half2_rn(o.z, o.w);
    }
}

// ---------------- final: out = raw * (1 + relu(ov)) ----------------
__global__ void final_kernel(const float* __restrict__ raw,
                             const float* __restrict__ ov,
                             float* __restrict__ out)
{
    int i = blockIdx.x * blockDim.x + threadIdx.x;
    float4 r = reinterpret_cast<const float4*>(raw)[i];
    float4 o = reinterpret_cast<const float4*>(ov)[i];
    float4 res;
    res.x = r.x * (1.f + fmaxf(o.x, 0.f));
    res.y = r.y * (1.f + fmaxf(o.y, 0.f));
    res.z = r.z * (1.f + fmaxf(o.z, 0.f));
    res.w = r.w * (1.f + fmaxf(o.w, 0.f));
    reinterpret_cast<float4*>(out)[i] = res;
}

// ---------------- launch ----------------
extern "C" void kernel_launch(void* const* d_in, const int* in_sizes, int n_in,
                              void* d_out, int out_size)
{
    const int*   x        = (const int*)  d_in[0];
    const float* adapt2_w = (const float*)d_in[1];
    const float* adapt2_b = (const float*)d_in[2];
    const float* adapt_w  = (const float*)d_in[3];
    const float* adapt_b  = (const float*)d_in[4];
    const float* qkv_w    = (const float*)d_in[5];
    const float* qkv_b    = (const float*)d_in[6];
    const float* out_w    = (const float*)d_in[7];
    const float* out_b    = (const float*)d_in[8];
    const float* ln1_g    = (const float*)d_in[9];
    const float* ln1_b    = (const float*)d_in[10];
    const float* lin1_w   = (const float*)d_in[11];
    const float* lin1_b   = (const float*)d_in[12];
    const float* lin2_w   = (const float*)d_in[13];
    const float* lin2_b   = (const float*)d_in[14];
    const float* ln2_g    = (const float*)d_in[15];
    const float* ln2_b    = (const float*)d_in[16];
    const float* fc_w     = (const float*)d_in[17];
    const float* fc_b     = (const float*)d_in[18];
    float* out = (float*)d_out;

    float  *h, *raw, *ov;
    __half *h16, *qkv16, *ctx16, *ff16, *y16, *wT16;
    cudaGetSymbolAddress((void**)&h,     g_h);
    cudaGetSymbolAddress((void**)&h16,   g_h16);
    cudaGetSymbolAddress((void**)&qkv16, g_qkv16);
    cudaGetSymbolAddress((void**)&ctx16, g_ctx16);
    cudaGetSymbolAddress((void**)&ff16,  g_ff16);
    cudaGetSymbolAddress((void**)&y16,   g_y16);
    cudaGetSymbolAddress((void**)&raw,   g_raw);
    cudaGetSymbolAddress((void**)&ov,    g_ov);
    cudaGetSymbolAddress((void**)&wT16,  g_wT16);

    cudaFuncSetAttribute(attn_kernel,    cudaFuncAttributeMaxDynamicSharedMemorySize, ATTN_SMEM);
    cudaFuncSetAttribute(gemm_mma<0, 0>, cudaFuncAttributeMaxDynamicSharedMemorySize, GEMM_SMEM);
    cudaFuncSetAttribute(gemm_mma<0, 1>, cudaFuncAttributeMaxDynamicSharedMemorySize, GEMM_SMEM);
    cudaFuncSetAttribute(gemm_mma<1, 1>, cudaFuncAttributeMaxDynamicSharedMemorySize, GEMM_SMEM);

    // transpose + fp16-convert all weights to [N, K]
    dim3 tb(32, 8);
    for (int l = 0; l < LL; l++) {
        transpose_kernel<<<dim3(1536 / 32, 512 / 32), tb>>>(qkv_w  + (size_t)l * DD * 3 * DD, wT16 + WT_QKV(l),  512, 1536);
        transpose_kernel<<<dim3(512 / 32,  512 / 32), tb>>>(out_w  + (size_t)l * DD * DD,     wT16 + WT_OUT(l),  512, 512);
        transpose_kernel<<<dim3(512 / 32,  512 / 32), tb>>>(lin1_w + (size_t)l * DD * FFD,    wT16 + WT_LIN1(l), 512, 512);
        transpose_kernel<<<dim3(512 / 32,  512 / 32), tb>>>(lin2_w + (size_t)l * FFD * DD,    wT16 + WT_LIN2(l), 512, 512);
    }
    transpose_kernel<<<dim3(512 / 32, 512 / 32), tb>>>(fc_w, wT16 + WT_FC, 512, 512);

    embed_kernel<<<NTOK, 128>>>(x, adapt_w, adapt_b, h, h16);
    raw_kernel<<<NSEQ, 128>>>(x, adapt2_w, adapt2_b, raw);

    for (int l = 0; l < LL; l++) {
        const float* qb  = qkv_b  + (size_t)l * 3 * DD;
        const float* ob  = out_b  + (size_t)l * DD;
        const float* l1b = lin1_b + (size_t)l * FFD;
        const float* l2b = lin2_b + (size_t)l * DD;

        // qkv = h @ qkv_w + b   -> fp16 (73728 x 1536)
        gemm_mma<0, 1><<<dim3(1536 / 128, NTOK / 128), 256, GEMM_SMEM>>>(h16, 512, wT16 + WT_QKV(l), qb, qkv16, 3 * DD);
        // ctx (fp16)
        attn_kernel<<<NSEQ, 256, ATTN_SMEM>>>(qkv16, ctx16);
        // y = ctx @ out_w + b   -> fp16
        gemm_mma<0, 1><<<dim3(DD / 128, NTOK / 128), 256, GEMM_SMEM>>>(ctx16, 512, wT16 + WT_OUT(l), ob, y16, DD);
        // h = LN(h + y)
        add_ln_kernel<<<NTOK / 8, 256>>>(h, h16, y16, ln1_g + (size_t)l * DD, ln1_b + (size_t)l * DD);
        // t = relu(h @ lin1 + b) -> fp16
        gemm_mma<1, 1><<<dim3(FFD / 128, NTOK / 128), 256, GEMM_SMEM>>>(h16, 512, wT16 + WT_LIN1(l), l1b, ff16, FFD);
        // y = t @ lin2 + b -> fp16
        gemm_mma<0, 1><<<dim3(DD / 128, NTOK / 128), 256, GEMM_SMEM>>>(ff16, 512, wT16 + WT_LIN2(l), l2b, y16, DD);
        // h = LN(h + y)
        add_ln_kernel<<<NTOK / 8, 256>>>(h, h16, y16, ln2_g + (size_t)l * DD, ln2_b + (size_t)l * DD);
    }

    // ov = cls @ fc_w + fc_b  (cls rows are h16[n*9,:], so lda = 9*512) -> fp32
    gemm_mma<0, 0><<<dim3(OUTD / 128, NSEQ / 128), 256, GEMM_SMEM>>>(h16, SS * DD, wT16 + WT_FC, fc_b, ov, OUTD);

    // out = raw * (1 + relu(ov))
    final_kernel<<<(NSEQ * OUTD / 4) / 256, 256>>>(raw, ov, out);
}

// round 15
// speedup vs baseline: 4.0491x; 1.0377x over previous
#include <cuda_runtime.h>
#include <cuda_fp16.h>
#include <cstdint>

// ---------------- problem constants ----------------
#define BB   32
#define TT   256
#define SS   9
#define EE   631
#define DD   512
#define FFD  512
#define HH   8
#define HDD  64
#define LL   2
#define OUTD 512
#define NSEQ (BB*TT)          // 8192 sequences
#define NTOK (NSEQ*SS)        // 73728 tokens
#define EPS  1e-5f

// ---------------- scratch (static device globals; no allocs) ----------------
__device__ float  g_h[(size_t)NTOK * DD];          // hidden state fp32
__device__ __half g_h16[(size_t)NTOK * DD];        // fp16 shadow of h
__device__ __half g_qkv16[(size_t)NTOK * 3 * DD];  // qkv (fp16)
__device__ __half g_ctx16[(size_t)NTOK * DD];      // attention ctx (fp16)
__device__ __half g_ff16[(size_t)NTOK * DD];       // relu(lin1) (fp16)
__device__ __half g_y16[(size_t)NTOK * DD];        // sublayer output y (fp16)
__device__ float  g_raw[(size_t)NSEQ * OUTD];      // raw_emb
__device__ float  g_ov[(size_t)NSEQ * OUTD];       // fc output
__device__ __half g_wT16[3407872];                 // transposed weights [N,K] fp16

// weight-transpose offsets (elements)
#define WT_QKV(l)  ((size_t)(l) * 786432)
#define WT_OUT(l)  (1572864 + (size_t)(l) * 262144)
#define WT_LIN1(l) (2097152 + (size_t)(l) * 262144)
#define WT_LIN2(l) (2621440 + (size_t)(l) * 262144)
#define WT_FC      (3145728)

// ---------------- PTX helpers (target-neutral, sm_80-era) ----------------
__device__ __forceinline__ unsigned smem_u32(const void* p) {
    unsigned a;
    asm("{ .reg .u64 t; cvta.to.shared.u64 t, %1; cvt.u32.u64 %0, t; }" : "=r"(a) : "l"(p));
    return a;
}
__device__ __forceinline__ void cp16(unsigned dst, const void* src) {
    asm volatile("cp.async.cg.shared.global [%0], [%1], 16;" :: "r"(dst), "l"(src) : "memory");
}
__device__ __forceinline__ void ldmx4(unsigned addr, unsigned &r0, unsigned &r1,
                                      unsigned &r2, unsigned &r3) {
    asm volatile("ldmatrix.sync.aligned.m8n8.x4.shared.b16 {%0,%1,%2,%3}, [%4];"
                 : "=r"(r0), "=r"(r1), "=r"(r2), "=r"(r3) : "r"(addr));
}
__device__ __forceinline__ void mma_f16(float& d0, float& d1, float& d2, float& d3,
                                        unsigned a0, unsigned a1, unsigned a2, unsigned a3,
                                        unsigned b0, unsigned b1) {
    asm volatile("mma.sync.aligned.m16n8k16.row.col.f32.f16.f16.f32 "
                 "{%0,%1,%2,%3}, {%4,%5,%6,%7}, {%8,%9}, {%0,%1,%2,%3};"
                 : "+f"(d0), "+f"(d1), "+f"(d2), "+f"(d3)
                 : "r"(a0), "r"(a1), "r"(a2), "r"(a3), "r"(b0), "r"(b1));
}

// ---------------- fp16 mma GEMM ----------------
// C[M,N] = act(A[M,K=512] @ BT[N,K=512]^T + bias)
// BM=128 BN=128 BK=32, 256 threads (8 warps, 4x2, warp tile 32x64),
// 4-stage cp.async pipeline, ldmatrix from 80B-padded SMEM rows,
// 2 CTAs/SM for latency hiding.
#define ST_A_BYTES (128 * 80)            // 10240
#define ST_BYTES   (2 * ST_A_BYTES)      // 20480 per stage
#define GEMM_SMEM  (4 * ST_BYTES)        // 81920

__device__ __forceinline__ void gemm_issue(unsigned st,
                                           const __half* __restrict__ A0, int lda,
                                           const __half* __restrict__ B0, int k0)
{
    const int tid = threadIdx.x;
#pragma unroll
    for (int i = 0; i < 2; i++) {
        int c = tid + i * 256;
        int row = c >> 2, seg = c & 3;
        cp16(st + row * 80 + seg * 16,              A0 + (size_t)row * lda + k0 + seg * 8);
        cp16(st + ST_A_BYTES + row * 80 + seg * 16, B0 + (size_t)row * 512 + k0 + seg * 8);
    }
    asm volatile("cp.async.commit_group;" ::: "memory");
}

template<int ACT, int OUT16>
__global__ __launch_bounds__(256, 2)
void gemm_mma(const __half* __restrict__ A, int lda,
              const __half* __restrict__ BT,
              const float* __restrict__ bias,
              void* __restrict__ Cv, int ldc)
{
    extern __shared__ char smem[];
    const unsigned sbase = smem_u32(smem);
    const int tid = threadIdx.x, lid = tid & 31, wid = tid >> 5;
    const int wm = wid & 3, wn = wid >> 2;      // 4 x 2 warp grid
    const int bx = blockIdx.x, by = blockIdx.y;

    const __half* Ab = A  + (size_t)by * 128 * lda;
    const __half* Bb = BT + (size_t)bx * 128 * 512;

    gemm_issue(sbase,                Ab, lda, Bb, 0);
    gemm_issue(sbase + ST_BYTES,     Ab, lda, Bb, 32);
    gemm_issue(sbase + 2 * ST_BYTES, Ab, lda, Bb, 64);

    float c[2][8][4];
#pragma unroll
    for (int i = 0; i < 2; i++)
#pragma unroll
        for (int j = 0; j < 8; j++)
#pragma unroll
            for (int q = 0; q < 4; q++) c[i][j][q] = 0.f;

    // per-lane ldmatrix offsets
    const unsigned a_row = lid & 15, a_k = (lid >> 4) * 8;
    const unsigned b_n = (lid & 7) + ((lid >> 4) << 3), b_k = ((lid >> 3) & 1) * 8;

#pragma unroll 1
    for (int k = 0; k < 16; k++) {
        asm volatile("cp.async.wait_group 2;" ::: "memory");
        __syncthreads();
        // issue next stage early: buffer (k+3)&3 == (k-1)&3 was fully consumed in iter k-1
        if (k < 13) gemm_issue(sbase + ((k + 3) & 3) * ST_BYTES, Ab, lda, Bb, (k + 3) * 32);
        else        asm volatile("cp.async.commit_group;" ::: "memory");  // uniform group count

        const unsigned sA = sbase + (k & 3) * ST_BYTES;
        const unsigned sB = sA + ST_A_BYTES;
#pragma unroll
        for (int ks = 0; ks < 2; ks++) {
            unsigned a[2][4], b[4][4];
#pragma unroll
            for (int i = 0; i < 2; i++)
                ldmx4(sA + (wm * 32 + i * 16 + a_row) * 80 + (ks * 16 + a_k) * 2,
                      a[i][0], a[i][1], a[i][2], a[i][3]);
#pragma unroll
            for (int jj = 0; jj < 4; jj++)
                ldmx4(sB + (wn * 64 + jj * 16 + b_n) * 80 + (ks * 16 + b_k) * 2,
                      b[jj][0], b[jj][1], b[jj][2], b[jj][3]);
#pragma unroll
            for (int i = 0; i < 2; i++)
#pragma unroll
                for (int j = 0; j < 8; j++)
                    mma_f16(c[i][j][0], c[i][j][1], c[i][j][2], c[i][j][3],
                            a[i][0], a[i][1], a[i][2], a[i][3],
                            b[j >> 1][(j & 1) * 2], b[j >> 1][(j & 1) * 2 + 1]);
        }
    }

    // ---------------- epilogue ----------------
    const int qrow = lid >> 2, qcol = (lid & 3) * 2;
    const int gcol = bx * 128 + wn * 64 + qcol;
    float2 bv[8];
#pragma unroll
    for (int j = 0; j < 8; j++) bv[j] = *reinterpret_cast<const float2*>(bias + gcol + j * 8);

    const size_t rbase = (size_t)by * 128 + wm * 32 + qrow;
#pragma unroll
    for (int i = 0; i < 2; i++) {
#pragma unroll
        for (int hh = 0; hh < 2; hh++) {
            size_t row = rbase + i * 16 + hh * 8;
#pragma unroll
            for (int j = 0; j < 8; j++) {
                float x = c[i][j][hh * 2 + 0] + bv[j].x;
                float y = c[i][j][hh * 2 + 1] + bv[j].y;
                if (ACT) { x = fmaxf(x, 0.f); y = fmaxf(y, 0.f); }
                if (OUT16) {
                    __half* p = (__half*)Cv + row * ldc + gcol + j * 8;
                    *reinterpret_cast<__half2*>(p) = __floats2half2_rn(x, y);
                } else {
                    float* p = (float*)Cv + row * ldc + gcol + j * 8;
                    *reinterpret_cast<float2*>(p) = make_float2(x, y);
                }
            }
        }
    }
}

// ---------------- batched weight transpose+convert: in[K=512,N] fp32 -> out[N,K] fp16 ----------------
struct TJobs {
    const float* src[9];
    __half*      dst[9];
    int          N[9];
};

__global__ void transpose_all_kernel(TJobs j)
{
    __shared__ float t[32][33];
    const int job = blockIdx.z;
    const int N = j.N[job];
    const int n0 = blockIdx.x * 32, k0 = blockIdx.y * 32;
    if (n0 >= N) return;
    const float* in = j.src[job];
    __half* out = j.dst[job];
    int x = threadIdx.x, y = threadIdx.y;     // 32 x 8
#pragma unroll
    for (int i = 0; i < 32; i += 8)
        t[y + i][x] = in[(size_t)(k0 + y + i) * N + n0 + x];
    __syncthreads();
#pragma unroll
    for (int i = 0; i < 32; i += 8)
        out[(size_t)(n0 + y + i) * 512 + k0 + x] = __float2half_rn(t[x][y + i]);
}

// ---------------- embedding gather ----------------
__global__ void embed_kernel(const int* __restrict__ x,
                             const float* __restrict__ w,
                             const float* __restrict__ b,
                             float* __restrict__ h, __half* __restrict__ h16)
{
    int i = blockIdx.x, t = threadIdx.x;     // NTOK blocks x 128 threads
    int e = x[i];
    float4 wv = reinterpret_cast<const float4*>(w)[(size_t)e * 128 + t];
    float4 bv = reinterpret_cast<const float4*>(b)[t];
    float4 r = make_float4(wv.x + bv.x, wv.y + bv.y, wv.z + bv.z, wv.w + bv.w);
    reinterpret_cast<float4*>(h)[(size_t)i * 128 + t] = r;
    __half2* hp = reinterpret_cast<__half2*>(h16 + (size_t)i * 512 + t * 4);
    hp[0] = __floats2half2_rn(r.x, r.y);
    hp[1] = __floats2half2_rn(r.z, r.w);
}

// ---------------- raw_emb ----------------
__global__ void raw_kernel(const int* __restrict__ x,
                           const float* __restrict__ w2,
                           const float* __restrict__ b2,
                           float* __restrict__ raw)
{
    int n = blockIdx.x, t = threadIdx.x;
    __shared__ int xs[SS];
    if (t < SS) xs[t] = x[n * SS + t];
    __syncthreads();
    float4 acc = reinterpret_cast<const float4*>(b2)[t];
#pragma unroll
    for (int s = 0; s < SS; s++) {
        float4 v = reinterpret_cast<const float4*>(w2)[((size_t)s * EE + xs[s]) * 128 + t];
        acc.x += v.x; acc.y += v.y; acc.z += v.z; acc.w += v.w;
    }
    reinterpret_cast<float4*>(raw)[(size_t)n * 128 + t] = acc;
}

// ---------------- attention: one CTA per sequence (fp16 in, fp32 math, fp16 out) ----------------
#define ROWP 516
#define ATTN_SMEM ((3 * SS * ROWP + HH * SS * SS) * 4)

__global__ __launch_bounds__(256)
void attn_kernel(const __half* __restrict__ qkv16, __half* __restrict__ ctx16)
{
    extern __shared__ float sm[];
    float* sq = sm;
    float* sk = sq + SS * ROWP;
    float* sv = sk + SS * ROWP;
    float* sc = sv + SS * ROWP;

    const int n = blockIdx.x, tid = threadIdx.x;

    const uint4* q16 = reinterpret_cast<const uint4*>(qkv16 + (size_t)n * SS * 1536);
    for (int u = tid; u < SS * 192; u += 256) {
        int s = u / 192, c8 = u % 192;
        uint4 rawv = q16[u];
        const __half2* hp = reinterpret_cast<const __half2*>(&rawv);
        float2 f0 = __half22float2(hp[0]), f1 = __half22float2(hp[1]);
        float2 f2 = __half22float2(hp[2]), f3 = __half22float2(hp[3]);
        int col = c8 * 8;
        float* dst;
        if (col < 512)       dst = sq + s * ROWP + col;
        else if (col < 1024) dst = sk + s * ROWP + (col - 512);
        else                 dst = sv + s * ROWP + (col - 1024);
        reinterpret_cast<float4*>(dst)[0] = make_float4(f0.x, f0.y, f1.x, f1.y);
        reinterpret_cast<float4*>(dst)[1] = make_float4(f2.x, f2.y, f3.x, f3.y);
    }
    __syncthreads();

    for (int p = tid; p < HH * SS * SS; p += 256) {
        int h = p / (SS * SS), rem = p % (SS * SS), i = rem / SS, j = rem % SS;
        const float* qp = sq + i * ROWP + h * HDD;
        const float* kp = sk + j * ROWP + h * HDD;
        float dot = 0.f;
#pragma unroll
        for (int d = 0; d < HDD; d++) dot += qp[d] * kp[d];
        sc[p] = dot * 0.125f;
    }
    __syncthreads();

    if (tid < HH * SS) {
        float* row = sc + tid * SS;
        float m = row[0];
#pragma unroll
        for (int j = 1; j < SS; j++) m = fmaxf(m, row[j]);
        float s2 = 0.f;
#pragma unroll
        for (int j = 0; j < SS; j++) { float e = __expf(row[j] - m); row[j] = e; s2 += e; }
        float inv = 1.f / s2;
#pragma unroll
        for (int j = 0; j < SS; j++) row[j] *= inv;
    }
    __syncthreads();

    __half* c16 = ctx16 + (size_t)n * SS * DD;
    for (int u = tid; u < SS * 128; u += 256) {
        int i = u >> 7, c4 = u & 127;
        int h = c4 >> 4;
        const float* arow = sc + (h * SS + i) * SS;
        float4 acc = make_float4(0.f, 0.f, 0.f, 0.f);
#pragma unroll
        for (int j = 0; j < SS; j++) {
            float a = arow[j];
            float4 vv = *reinterpret_cast<const float4*>(sv + j * ROWP + c4 * 4);
            acc.x += a * vv.x; acc.y += a * vv.y; acc.z += a * vv.z; acc.w += a * vv.w;
        }
        __half2* cp2 = reinterpret_cast<__half2*>(c16 + i * 512 + c4 * 4);
        cp2[0] = __floats2half2_rn(acc.x, acc.y);
        cp2[1] = __floats2half2_rn(acc.z, acc.w);
    }
}

// ---------------- fused residual + layernorm (+ fp16 shadow) ----------------
__global__ __launch_bounds__(256)
void add_ln_kernel(float* __restrict__ h, __half* __restrict__ h16,
                   const __half* __restrict__ y16,
                   const float* __restrict__ gamma, const float* __restrict__ beta)
{
    int warp = threadIdx.x >> 5, lane = threadIdx.x & 31;
    size_t row = (size_t)blockIdx.x * 8 + warp;
    float4* h4        = reinterpret_cast<float4*>(h) + row * 128;
    const __half2* y2 = reinterpret_cast<const __half2*>(y16) + row * 256;

    float4 xv[4];
    float sum = 0.f, sq = 0.f;
#pragma unroll
    for (int q = 0; q < 4; q++) {
        float4 a = h4[q * 32 + lane];
        __half2 ya = y2[(q * 32 + lane) * 2], yb = y2[(q * 32 + lane) * 2 + 1];
        float2 fa = __half22float2(ya), fb = __half22float2(yb);
        float4 v = make_float4(a.x + fa.x, a.y + fa.y, a.z + fb.x, a.w + fb.y);
        xv[q] = v;
        sum += v.x + v.y + v.z + v.w;
        sq  += v.x * v.x + v.y * v.y + v.z * v.z + v.w * v.w;
    }
#pragma unroll
    for (int o = 16; o > 0; o >>= 1) {
        sum += __shfl_xor_sync(0xffffffffu, sum, o);
        sq  += __shfl_xor_sync(0xffffffffu, sq,  o);
    }
    float mean = sum * (1.f / 512.f);
    float var  = sq * (1.f / 512.f) - mean * mean;
    float rstd = rsqrtf(var + EPS);

    const float4* g4 = reinterpret_cast<const float4*>(gamma);
    const float4* b4 = reinterpret_cast<const float4*>(beta);
    __half2* hp = reinterpret_cast<__half2*>(h16) + row * 256;
#pragma unroll
    for (int q = 0; q < 4; q++) {
        float4 g = g4[q * 32 + lane], bb = b4[q * 32 + lane], v = xv[q];
        float4 o;
        o.x = (v.x - mean) * rstd * g.x + bb.x;
        o.y = (v.y - mean) * rstd * g.y + bb.y;
        o.z = (v.z - mean) * rstd * g.z + bb.z;
        o.w = (v.w - mean) * rstd * g.w + bb.w;
        h4[q * 32 + lane] = o;
        hp[(q * 32 + lane) * 2]     = __floats2half2_rn(o.x, o.y);
        hp[(q * 32 + lane) * 2 + 1] = __floats2half2_rn(o.z, o.w);
    }
}

// ---------------- final: out = raw * (1 + relu(ov)) ----------------
__global__ void final_kernel(const float* __restrict__ raw,
                             const float* __restrict__ ov,
                             float* __restrict__ out)
{
    int i = blockIdx.x * blockDim.x + threadIdx.x;
    float4 r = reinterpret_cast<const float4*>(raw)[i];
    float4 o = reinterpret_cast<const float4*>(ov)[i];
    float4 res;
    res.x = r.x * (1.f + fmaxf(o.x, 0.f));
    res.y = r.y * (1.f + fmaxf(o.y, 0.f));
    res.z = r.z * (1.f + fmaxf(o.z, 0.f));
    res.w = r.w * (1.f + fmaxf(o.w, 0.f));
    reinterpret_cast<float4*>(out)[i] = res;
}

// ---------------- launch ----------------
extern "C" void kernel_launch(void* const* d_in, const int* in_sizes, int n_in,
                              void* d_out, int out_size)
{
    const int*   x        = (const int*)  d_in[0];
    const float* adapt2_w = (const float*)d_in[1];
    const float* adapt2_b = (const float*)d_in[2];
    const float* adapt_w  = (const float*)d_in[3];
    const float* adapt_b  = (const float*)d_in[4];
    const float* qkv_w    = (const float*)d_in[5];
    const float* qkv_b    = (const float*)d_in[6];
    const float* out_w    = (const float*)d_in[7];
    const float* out_b    = (const float*)d_in[8];
    const float* ln1_g    = (const float*)d_in[9];
    const float* ln1_b    = (const float*)d_in[10];
    const float* lin1_w   = (const float*)d_in[11];
    const float* lin1_b   = (const float*)d_in[12];
    const float* lin2_w   = (const float*)d_in[13];
    const float* lin2_b   = (const float*)d_in[14];
    const float* ln2_g    = (const float*)d_in[15];
    const float* ln2_b    = (const float*)d_in[16];
    const float* fc_w     = (const float*)d_in[17];
    const float* fc_b     = (const float*)d_in[18];
    float* out = (float*)d_out;

    float  *h, *raw, *ov;
    __half *h16, *qkv16, *ctx16, *ff16, *y16, *wT16;
    cudaGetSymbolAddress((void**)&h,     g_h);
    cudaGetSymbolAddress((void**)&h16,   g_h16);
    cudaGetSymbolAddress((void**)&qkv16, g_qkv16);
    cudaGetSymbolAddress((void**)&ctx16, g_ctx16);
    cudaGetSymbolAddress((void**)&ff16,  g_ff16);
    cudaGetSymbolAddress((void**)&y16,   g_y16);
    cudaGetSymbolAddress((void**)&raw,   g_raw);
    cudaGetSymbolAddress((void**)&ov,    g_ov);
    cudaGetSymbolAddress((void**)&wT16,  g_wT16);

    cudaFuncSetAttribute(attn_kernel,    cudaFuncAttributeMaxDynamicSharedMemorySize, ATTN_SMEM);
    cudaFuncSetAttribute(gemm_mma<0, 0>, cudaFuncAttributeMaxDynamicSharedMemorySize, GEMM_SMEM);
    cudaFuncSetAttribute(gemm_mma<0, 1>, cudaFuncAttributeMaxDynamicSharedMemorySize, GEMM_SMEM);
    cudaFuncSetAttribute(gemm_mma<1, 1>, cudaFuncAttributeMaxDynamicSharedMemorySize, GEMM_SMEM);

    // one batched transpose+convert launch for all 9 weight matrices
    TJobs tj;
    tj.src[0] = qkv_w;                          tj.dst[0] = wT16 + WT_QKV(0);  tj.N[0] = 1536;
    tj.src[1] = qkv_w + (size_t)DD * 3 * DD;    tj.dst[1] = wT16 + WT_QKV(1);  tj.N[1] = 1536;
    tj.src[2] = out_w;                          tj.dst[2] = wT16 + WT_OUT(0);  tj.N[2] = 512;
    tj.src[3] = out_w + (size_t)DD * DD;        tj.dst[3] = wT16 + WT_OUT(1);  tj.N[3] = 512;
    tj.src[4] = lin1_w;                         tj.dst[4] = wT16 + WT_LIN1(0); tj.N[4] = 512;
    tj.src[5] = lin1_w + (size_t)DD * FFD;      tj.dst[5] = wT16 + WT_LIN1(1); tj.N[5] = 512;
    tj.src[6] = lin2_w;                         tj.dst[6] = wT16 + WT_LIN2(0); tj.N[6] = 512;
    tj.src[7] = lin2_w + (size_t)FFD * DD;      tj.dst[7] = wT16 + WT_LIN2(1); tj.N[7] = 512;
    tj.src[8] = fc_w;                           tj.dst[8] = wT16 + WT_FC;      tj.N[8] = 512;
    transpose_all_kernel<<<dim3(1536 / 32, 512 / 32, 9), dim3(32, 8)>>>(tj);

    embed_kernel<<<NTOK, 128>>>(x, adapt_w, adapt_b, h, h16);
    raw_kernel<<<NSEQ, 128>>>(x, adapt2_w, adapt2_b, raw);

    for (int l = 0; l < LL; l++) {
        const float* qb  = qkv_b  + (size_t)l * 3 * DD;
        const float* ob  = out_b  + (size_t)l * DD;
        const float* l1b = lin1_b + (size_t)l * FFD;
        const float* l2b = lin2_b + (size_t)l * DD;

        // qkv = h @ qkv_w + b   -> fp16 (73728 x 1536)
        gemm_mma<0, 1><<<dim3(1536 / 128, NTOK / 128), 256, GEMM_SMEM>>>(h16, 512, wT16 + WT_QKV(l), qb, qkv16, 3 * DD);
        // ctx (fp16)
        attn_kernel<<<NSEQ, 256, ATTN_SMEM>>>(qkv16, ctx16);
        // y = ctx @ out_w + b   -> fp16
        gemm_mma<0, 1><<<dim3(DD / 128, NTOK / 128), 256, GEMM_SMEM>>>(ctx16, 512, wT16 + WT_OUT(l), ob, y16, DD);
        // h = LN(h + y)
        add_ln_kernel<<<NTOK / 8, 256>>>(h, h16, y16, ln1_g + (size_t)l * DD, ln1_b + (size_t)l * DD);
        // t = relu(h @ lin1 + b) -> fp16
        gemm_mma<1, 1><<<dim3(FFD / 128, NTOK / 128), 256, GEMM_SMEM>>>(h16, 512, wT16 + WT_LIN1(l), l1b, ff16, FFD);
        // y = t @ lin2 + b -> fp16
        gemm_mma<0, 1><<<dim3(DD / 128, NTOK / 128), 256, GEMM_SMEM>>>(ff16, 512, wT16 + WT_LIN2(l), l2b, y16, DD);
        // h = LN(h + y)
        add_ln_kernel<<<NTOK / 8, 256>>>(h, h16, y16, ln2_g + (size_t)l * DD, ln2_b + (size_t)l * DD);
    }

    // ov = cls @ fc_w + fc_b  (cls rows are h16[n*9,:], so lda = 9*512) -> fp32
    gemm_mma<0, 0><<<dim3(OUTD / 128, NSEQ / 128), 256, GEMM_SMEM>>>(h16, SS * DD, wT16 + WT_FC, fc_b, ov, OUTD);

    // out = raw * (1 + relu(ov))
    final_kernel<<<(NSEQ * OUTD / 4) / 256, 256>>>(raw, ov, out);
}

// round 16
// speedup vs baseline: 4.3825x; 1.0823x over previous
#include <cuda_runtime.h>
#include <cuda_fp16.h>
#include <cstdint>

// ---------------- problem constants ----------------
#define BB   32
#define TT   256
#define SS   9
#define EE   631
#define DD   512
#define FFD  512
#define HH   8
#define HDD  64
#define LL   2
#define OUTD 512
#define NSEQ (BB*TT)          // 8192 sequences
#define NTOK (NSEQ*SS)        // 73728 tokens
#define EPS  1e-5f

// ---------------- scratch (static device globals; no allocs) ----------------
__device__ float  g_h[(size_t)NTOK * DD];          // hidden state fp32
__device__ __half g_h16[(size_t)NTOK * DD];        // fp16 shadow of h
__device__ __half g_qkv16[(size_t)NTOK * 3 * DD];  // qkv (fp16)
__device__ __half g_ctx16[(size_t)NTOK * DD];      // attention ctx (fp16)
__device__ __half g_ff16[(size_t)NTOK * DD];       // relu(lin1) (fp16)
__device__ __half g_y16[(size_t)NTOK * DD];        // sublayer output y (fp16)
__device__ float  g_raw[(size_t)NSEQ * OUTD];      // raw_emb
__device__ float  g_ov[(size_t)NSEQ * OUTD];       // fc output
__device__ __half g_wT16[3407872];                 // transposed weights [N,K] fp16

// weight-transpose offsets (elements)
#define WT_QKV(l)  ((size_t)(l) * 786432)
#define WT_OUT(l)  (1572864 + (size_t)(l) * 262144)
#define WT_LIN1(l) (2097152 + (size_t)(l) * 262144)
#define WT_LIN2(l) (2621440 + (size_t)(l) * 262144)
#define WT_FC      (3145728)

// ---------------- PTX helpers (target-neutral, sm_80-era) ----------------
__device__ __forceinline__ unsigned smem_u32(const void* p) {
    unsigned a;
    asm("{ .reg .u64 t; cvta.to.shared.u64 t, %1; cvt.u32.u64 %0, t; }" : "=r"(a) : "l"(p));
    return a;
}
__device__ __forceinline__ void cp16(unsigned dst, const void* src) {
    asm volatile("cp.async.cg.shared.global [%0], [%1], 16;" :: "r"(dst), "l"(src) : "memory");
}
__device__ __forceinline__ void ldmx4(unsigned addr, unsigned &r0, unsigned &r1,
                                      unsigned &r2, unsigned &r3) {
    asm volatile("ldmatrix.sync.aligned.m8n8.x4.shared.b16 {%0,%1,%2,%3}, [%4];"
                 : "=r"(r0), "=r"(r1), "=r"(r2), "=r"(r3) : "r"(addr));
}
__device__ __forceinline__ void mma_f16(float& d0, float& d1, float& d2, float& d3,
                                        unsigned a0, unsigned a1, unsigned a2, unsigned a3,
                                        unsigned b0, unsigned b1) {
    asm volatile("mma.sync.aligned.m16n8k16.row.col.f32.f16.f16.f32 "
                 "{%0,%1,%2,%3}, {%4,%5,%6,%7}, {%8,%9}, {%0,%1,%2,%3};"
                 : "+f"(d0), "+f"(d1), "+f"(d2), "+f"(d3)
                 : "r"(a0), "r"(a1), "r"(a2), "r"(a3), "r"(b0), "r"(b1));
}

// ---------------- fp16 mma GEMM ----------------
// C[M,N] = act(A[M,K=512] @ BT[N,K=512]^T + bias)
// BM=128 BN=128 BK=64, 256 threads (8 warps, 4x2, warp tile 32x64),
// 3-stage cp.async pipeline (8 mainloop iterations), 144B-padded SMEM rows,
// 2 CTAs/SM.
#define ST_A_BYTES (128 * 144)           // 18432
#define ST_BYTES   (2 * ST_A_BYTES)      // 36864 per stage
#define GEMM_SMEM  (3 * ST_BYTES)        // 110592

__device__ __forceinline__ void gemm_issue(unsigned st,
                                           const __half* __restrict__ A0, int lda,
                                           const __half* __restrict__ B0, int k0)
{
    const int tid = threadIdx.x;
#pragma unroll
    for (int i = 0; i < 4; i++) {
        int c = tid + i * 256;
        int row = c >> 3, seg = c & 7;
        cp16(st + row * 144 + seg * 16,              A0 + (size_t)row * lda + k0 + seg * 8);
        cp16(st + ST_A_BYTES + row * 144 + seg * 16, B0 + (size_t)row * 512 + k0 + seg * 8);
    }
    asm volatile("cp.async.commit_group;" ::: "memory");
}

template<int ACT, int OUT16>
__global__ __launch_bounds__(256, 2)
void gemm_mma(const __half* __restrict__ A, int lda,
              const __half* __restrict__ BT,
              const float* __restrict__ bias,
              void* __restrict__ Cv, int ldc)
{
    extern __shared__ char smem[];
    const unsigned sbase = smem_u32(smem);
    const int tid = threadIdx.x, lid = tid & 31, wid = tid >> 5;
    const int wm = wid & 3, wn = wid >> 2;      // 4 x 2 warp grid
    const int bx = blockIdx.x, by = blockIdx.y;

    const __half* Ab = A  + (size_t)by * 128 * lda;
    const __half* Bb = BT + (size_t)bx * 128 * 512;

    gemm_issue(sbase,            Ab, lda, Bb, 0);
    gemm_issue(sbase + ST_BYTES, Ab, lda, Bb, 64);

    float c[2][8][4];
#pragma unroll
    for (int i = 0; i < 2; i++)
#pragma unroll
        for (int j = 0; j < 8; j++)
#pragma unroll
            for (int q = 0; q < 4; q++) c[i][j][q] = 0.f;

    // per-lane ldmatrix offsets
    const unsigned a_row = lid & 15, a_k = (lid >> 4) * 8;
    const unsigned b_n = (lid & 7) + ((lid >> 4) << 3), b_k = ((lid >> 3) & 1) * 8;

#pragma unroll 1
    for (int k = 0; k < 8; k++) {
        asm volatile("cp.async.wait_group 1;" ::: "memory");
        __syncthreads();
        // buffer (k+2)%3 == (k-1)%3 was fully consumed in iter k-1 (barrier above ensures all warps done)
        if (k < 6) gemm_issue(sbase + ((k + 2) % 3) * ST_BYTES, Ab, lda, Bb, (k + 2) * 64);
        else       asm volatile("cp.async.commit_group;" ::: "memory");  // uniform group count

        const unsigned sA = sbase + (k % 3) * ST_BYTES;
        const unsigned sB = sA + ST_A_BYTES;
#pragma unroll
        for (int ks = 0; ks < 4; ks++) {
            unsigned a[2][4], b[4][4];
#pragma unroll
            for (int i = 0; i < 2; i++)
                ldmx4(sA + (wm * 32 + i * 16 + a_row) * 144 + (ks * 16 + a_k) * 2,
                      a[i][0], a[i][1], a[i][2], a[i][3]);
#pragma unroll
            for (int jj = 0; jj < 4; jj++)
                ldmx4(sB + (wn * 64 + jj * 16 + b_n) * 144 + (ks * 16 + b_k) * 2,
                      b[jj][0], b[jj][1], b[jj][2], b[jj][3]);
#pragma unroll
            for (int i = 0; i < 2; i++)
#pragma unroll
                for (int j = 0; j < 8; j++)
                    mma_f16(c[i][j][0], c[i][j][1], c[i][j][2], c[i][j][3],
                            a[i][0], a[i][1], a[i][2], a[i][3],
                            b[j >> 1][(j & 1) * 2], b[j >> 1][(j & 1) * 2 + 1]);
        }
    }

    // ---------------- epilogue ----------------
    const int qrow = lid >> 2, qcol = (lid & 3) * 2;
    const int gcol = bx * 128 + wn * 64 + qcol;
    float2 bv[8];
#pragma unroll
    for (int j = 0; j < 8; j++) bv[j] = *reinterpret_cast<const float2*>(bias + gcol + j * 8);

    const size_t rbase = (size_t)by * 128 + wm * 32 + qrow;
#pragma unroll
    for (int i = 0; i < 2; i++) {
#pragma unroll
        for (int hh = 0; hh < 2; hh++) {
            size_t row = rbase + i * 16 + hh * 8;
#pragma unroll
            for (int j = 0; j < 8; j++) {
                float x = c[i][j][hh * 2 + 0] + bv[j].x;
                float y = c[i][j][hh * 2 + 1] + bv[j].y;
                if (ACT) { x = fmaxf(x, 0.f); y = fmaxf(y, 0.f); }
                if (OUT16) {
                    __half* p = (__half*)Cv + row * ldc + gcol + j * 8;
                    *reinterpret_cast<__half2*>(p) = __floats2half2_rn(x, y);
                } else {
                    float* p = (float*)Cv + row * ldc + gcol + j * 8;
                    *reinterpret_cast<float2*>(p) = make_float2(x, y);
                }
            }
        }
    }
}

// ---------------- batched weight transpose+convert: in[K=512,N] fp32 -> out[N,K] fp16 ----------------
struct TJobs {
    const float* src[9];
    __half*      dst[9];
    int          N[9];
};

__global__ void transpose_all_kernel(TJobs j)
{
    __shared__ float t[32][33];
    const int job = blockIdx.z;
    const int N = j.N[job];
    const int n0 = blockIdx.x * 32, k0 = blockIdx.y * 32;
    if (n0 >= N) return;
    const float* in = j.src[job];
    __half* out = j.dst[job];
    int x = threadIdx.x, y = threadIdx.y;     // 32 x 8
#pragma unroll
    for (int i = 0; i < 32; i += 8)
        t[y + i][x] = in[(size_t)(k0 + y + i) * N + n0 + x];
    __syncthreads();
#pragma unroll
    for (int i = 0; i < 32; i += 8)
        out[(size_t)(n0 + y + i) * 512 + k0 + x] = __float2half_rn(t[x][y + i]);
}

// ---------------- embedding gather ----------------
__global__ void embed_kernel(const int* __restrict__ x,
                             const float* __restrict__ w,
                             const float* __restrict__ b,
                             float* __restrict__ h, __half* __restrict__ h16)
{
    int i = blockIdx.x, t = threadIdx.x;     // NTOK blocks x 128 threads
    int e = x[i];
    float4 wv = reinterpret_cast<const float4*>(w)[(size_t)e * 128 + t];
    float4 bv = reinterpret_cast<const float4*>(b)[t];
    float4 r = make_float4(wv.x + bv.x, wv.y + bv.y, wv.z + bv.z, wv.w + bv.w);
    reinterpret_cast<float4*>(h)[(size_t)i * 128 + t] = r;
    __half2* hp = reinterpret_cast<__half2*>(h16 + (size_t)i * 512 + t * 4);
    hp[0] = __floats2half2_rn(r.x, r.y);
    hp[1] = __floats2half2_rn(r.z, r.w);
}

// ---------------- raw_emb ----------------
__global__ void raw_kernel(const int* __restrict__ x,
                           const float* __restrict__ w2,
                           const float* __restrict__ b2,
                           float* __restrict__ raw)
{
    int n = blockIdx.x, t = threadIdx.x;
    __shared__ int xs[SS];
    if (t < SS) xs[t] = x[n * SS + t];
    __syncthreads();
    float4 acc = reinterpret_cast<const float4*>(b2)[t];
#pragma unroll
    for (int s = 0; s < SS; s++) {
        float4 v = reinterpret_cast<const float4*>(w2)[((size_t)s * EE + xs[s]) * 128 + t];
        acc.x += v.x; acc.y += v.y; acc.z += v.z; acc.w += v.w;
    }
    reinterpret_cast<float4*>(raw)[(size_t)n * 128 + t] = acc;
}

// ---------------- attention: one CTA per sequence (fp16 in, fp32 math, fp16 out) ----------------
#define ROWP 516
#define ATTN_SMEM ((3 * SS * ROWP + HH * SS * SS) * 4)

__global__ __launch_bounds__(256)
void attn_kernel(const __half* __restrict__ qkv16, __half* __restrict__ ctx16)
{
    extern __shared__ float sm[];
    float* sq = sm;
    float* sk = sq + SS * ROWP;
    float* sv = sk + SS * ROWP;
    float* sc = sv + SS * ROWP;

    const int n = blockIdx.x, tid = threadIdx.x;

    const uint4* q16 = reinterpret_cast<const uint4*>(qkv16 + (size_t)n * SS * 1536);
    for (int u = tid; u < SS * 192; u += 256) {
        int s = u / 192, c8 = u % 192;
        uint4 rawv = q16[u];
        const __half2* hp = reinterpret_cast<const __half2*>(&rawv);
        float2 f0 = __half22float2(hp[0]), f1 = __half22float2(hp[1]);
        float2 f2 = __half22float2(hp[2]), f3 = __half22float2(hp[3]);
        int col = c8 * 8;
        float* dst;
        if (col < 512)       dst = sq + s * ROWP + col;
        else if (col < 1024) dst = sk + s * ROWP + (col - 512);
        else                 dst = sv + s * ROWP + (col - 1024);
        reinterpret_cast<float4*>(dst)[0] = make_float4(f0.x, f0.y, f1.x, f1.y);
        reinterpret_cast<float4*>(dst)[1] = make_float4(f2.x, f2.y, f3.x, f3.y);
    }
    __syncthreads();

    for (int p = tid; p < HH * SS * SS; p += 256) {
        int h = p / (SS * SS), rem = p % (SS * SS), i = rem / SS, j = rem % SS;
        const float* qp = sq + i * ROWP + h * HDD;
        const float* kp = sk + j * ROWP + h * HDD;
        float dot = 0.f;
#pragma unroll
        for (int d = 0; d < HDD; d++) dot += qp[d] * kp[d];
        sc[p] = dot * 0.125f;
    }
    __syncthreads();

    if (tid < HH * SS) {
        float* row = sc + tid * SS;
        float m = row[0];
#pragma unroll
        for (int j = 1; j < SS; j++) m = fmaxf(m, row[j]);
        float s2 = 0.f;
#pragma unroll
        for (int j = 0; j < SS; j++) { float e = __expf(row[j] - m); row[j] = e; s2 += e; }
        float inv = 1.f / s2;
#pragma unroll
        for (int j = 0; j < SS; j++) row[j] *= inv;
    }
    __syncthreads();

    __half* c16 = ctx16 + (size_t)n * SS * DD;
    for (int u = tid; u < SS * 128; u += 256) {
        int i = u >> 7, c4 = u & 127;
        int h = c4 >> 4;
        const float* arow = sc + (h * SS + i) * SS;
        float4 acc = make_float4(0.f, 0.f, 0.f, 0.f);
#pragma unroll
        for (int j = 0; j < SS; j++) {
            float a = arow[j];
            float4 vv = *reinterpret_cast<const float4*>(sv + j * ROWP + c4 * 4);
            acc.x += a * vv.x; acc.y += a * vv.y; acc.z += a * vv.z; acc.w += a * vv.w;
        }
        __half2* cp2 = reinterpret_cast<__half2*>(c16 + i * 512 + c4 * 4);
        cp2[0] = __floats2half2_rn(acc.x, acc.y);
        cp2[1] = __floats2half2_rn(acc.z, acc.w);
    }
}

// ---------------- fused residual + layernorm (+ fp16 shadow) ----------------
__global__ __launch_bounds__(256)
void add_ln_kernel(float* __restrict__ h, __half* __restrict__ h16,
                   const __half* __restrict__ y16,
                   const float* __restrict__ gamma, const float* __restrict__ beta)
{
    int warp = threadIdx.x >> 5, lane = threadIdx.x & 31;
    size_t row = (size_t)blockIdx.x * 8 + warp;
    float4* h4        = reinterpret_cast<float4*>(h) + row * 128;
    const __half2* y2 = reinterpret_cast<const __half2*>(y16) + row * 256;

    float4 xv[4];
    float sum = 0.f, sq = 0.f;
#pragma unroll
    for (int q = 0; q < 4; q++) {
        float4 a = h4[q * 32 + lane];
        __half2 ya = y2[(q * 32 + lane) * 2], yb = y2[(q * 32 + lane) * 2 + 1];
        float2 fa = __half22float2(ya), fb = __half22float2(yb);
        float4 v = make_float4(a.x + fa.x, a.y + fa.y, a.z + fb.x, a.w + fb.y);
        xv[q] = v;
        sum += v.x + v.y + v.z + v.w;
        sq  += v.x * v.x + v.y * v.y + v.z * v.z + v.w * v.w;
    }
#pragma unroll
    for (int o = 16; o > 0; o >>= 1) {
        sum += __shfl_xor_sync(0xffffffffu, sum, o);
        sq  += __shfl_xor_sync(0xffffffffu, sq,  o);
    }
    float mean = sum * (1.f / 512.f);
    float var  = sq * (1.f / 512.f) - mean * mean;
    float rstd = rsqrtf(var + EPS);

    const float4* g4 = reinterpret_cast<const float4*>(gamma);
    const float4* b4 = reinterpret_cast<const float4*>(beta);
    __half2* hp = reinterpret_cast<__half2*>(h16) + row * 256;
#pragma unroll
    for (int q = 0; q < 4; q++) {
        float4 g = g4[q * 32 + lane], bb = b4[q * 32 + lane], v = xv[q];
        float4 o;
        o.x = (v.x - mean) * rstd * g.x + bb.x;
        o.y = (v.y - mean) * rstd * g.y + bb.y;
        o.z = (v.z - mean) * rstd * g.z + bb.z;
        o.w = (v.w - mean) * rstd * g.w + bb.w;
        h4[q * 32 + lane] = o;
        hp[(q * 32 + lane) * 2]     = __floats2half2_rn(o.x, o.y);
        hp[(q * 32 + lane) * 2 + 1] = __floats2half2_rn(o.z, o.w);
    }
}

// ---------------- final: out = raw * (1 + relu(ov)) ----------------
__global__ void final_kernel(const float* __restrict__ raw,
                             const float* __restrict__ ov,
                             float* __restrict__ out)
{
    int i = blockIdx.x * blockDim.x + threadIdx.x;
    float4 r = reinterpret_cast<const float4*>(raw)[i];
    float4 o = reinterpret_cast<const float4*>(ov)[i];
    float4 res;
    res.x = r.x * (1.f + fmaxf(o.x, 0.f));
    res.y = r.y * (1.f + fmaxf(o.y, 0.f));
    res.z = r.z * (1.f + fmaxf(o.z, 0.f));
    res.w = r.w * (1.f + fmaxf(o.w, 0.f));
    reinterpret_cast<float4*>(out)[i] = res;
}

// ---------------- launch ----------------
extern "C" void kernel_launch(void* const* d_in, const int* in_sizes, int n_in,
                              void* d_out, int out_size)
{
    const int*   x        = (const int*)  d_in[0];
    const float* adapt2_w = (const float*)d_in[1];
    const float* adapt2_b = (const float*)d_in[2];
    const float* adapt_w  = (const float*)d_in[3];
    const float* adapt_b  = (const float*)d_in[4];
    const float* qkv_w    = (const float*)d_in[5];
    const float* qkv_b    = (const float*)d_in[6];
    const float* out_w    = (const float*)d_in[7];
    const float* out_b    = (const float*)d_in[8];
    const float* ln1_g    = (const float*)d_in[9];
    const float* ln1_b    = (const float*)d_in[10];
    const float* lin1_w   = (const float*)d_in[11];
    const float* lin1_b   = (const float*)d_in[12];
    const float* lin2_w   = (const float*)d_in[13];
    const float* lin2_b   = (const float*)d_in[14];
    const float* ln2_g    = (const float*)d_in[15];
    const float* ln2_b    = (const float*)d_in[16];
    const float* fc_w     = (const float*)d_in[17];
    const float* fc_b     = (const float*)d_in[18];
    float* out = (float*)d_out;

    float  *h, *raw, *ov;
    __half *h16, *qkv16, *ctx16, *ff16, *y16, *wT16;
    cudaGetSymbolAddress((void**)&h,     g_h);
    cudaGetSymbolAddress((void**)&h16,   g_h16);
    cudaGetSymbolAddress((void**)&qkv16, g_qkv16);
    cudaGetSymbolAddress((void**)&ctx16, g_ctx16);
    cudaGetSymbolAddress((void**)&ff16,  g_ff16);
    cudaGetSymbolAddress((void**)&y16,   g_y16);
    cudaGetSymbolAddress((void**)&raw,   g_raw);
    cudaGetSymbolAddress((void**)&ov,    g_ov);
    cudaGetSymbolAddress((void**)&wT16,  g_wT16);

    cudaFuncSetAttribute(attn_kernel,    cudaFuncAttributeMaxDynamicSharedMemorySize, ATTN_SMEM);
    cudaFuncSetAttribute(gemm_mma<0, 0>, cudaFuncAttributeMaxDynamicSharedMemorySize, GEMM_SMEM);
    cudaFuncSetAttribute(gemm_mma<0, 1>, cudaFuncAttributeMaxDynamicSharedMemorySize, GEMM_SMEM);
    cudaFuncSetAttribute(gemm_mma<1, 1>, cudaFuncAttributeMaxDynamicSharedMemorySize, GEMM_SMEM);

    // one batched transpose+convert launch for all 9 weight matrices
    TJobs tj;
    tj.src[0] = qkv_w;                          tj.dst[0] = wT16 + WT_QKV(0);  tj.N[0] = 1536;
    tj.src[1] = qkv_w + (size_t)DD * 3 * DD;    tj.dst[1] = wT16 + WT_QKV(1);  tj.N[1] = 1536;
    tj.src[2] = out_w;                          tj.dst[2] = wT16 + WT_OUT(0);  tj.N[2] = 512;
    tj.src[3] = out_w + (size_t)DD * DD;        tj.dst[3] = wT16 + WT_OUT(1);  tj.N[3] = 512;
    tj.src[4] = lin1_w;                         tj.dst[4] = wT16 + WT_LIN1(0); tj.N[4] = 512;
    tj.src[5] = lin1_w + (size_t)DD * FFD;      tj.dst[5] = wT16 + WT_LIN1(1); tj.N[5] = 512;
    tj.src[6] = lin2_w;                         tj.dst[6] = wT16 + WT_LIN2(0); tj.N[6] = 512;
    tj.src[7] = lin2_w + (size_t)FFD * DD;      tj.dst[7] = wT16 + WT_LIN2(1); tj.N[7] = 512;
    tj.src[8] = fc_w;                           tj.dst[8] = wT16 + WT_FC;      tj.N[8] = 512;
    transpose_all_kernel<<<dim3(1536 / 32, 512 / 32, 9), dim3(32, 8)>>>(tj);

    embed_kernel<<<NTOK, 128>>>(x, adapt_w, adapt_b, h, h16);
    raw_kernel<<<NSEQ, 128>>>(x, adapt2_w, adapt2_b, raw);

    for (int l = 0; l < LL; l++) {
        const float* qb  = qkv_b  + (size_t)l * 3 * DD;
        const float* ob  = out_b  + (size_t)l * DD;
        const float* l1b = lin1_b + (size_t)l * FFD;
        const float* l2b = lin2_b + (size_t)l * DD;

        // qkv = h @ qkv_w + b   -> fp16 (73728 x 1536)
        gemm_mma<0, 1><<<dim3(1536 / 128, NTOK / 128), 256, GEMM_SMEM>>>(h16, 512, wT16 + WT_QKV(l), qb, qkv16, 3 * DD);
        // ctx (fp16)
        attn_kernel<<<NSEQ, 256, ATTN_SMEM>>>(qkv16, ctx16);
        // y = ctx @ out_w + b   -> fp16
        gemm_mma<0, 1><<<dim3(DD / 128, NTOK / 128), 256, GEMM_SMEM>>>(ctx16, 512, wT16 + WT_OUT(l), ob, y16, DD);
        // h = LN(h + y)
        add_ln_kernel<<<NTOK / 8, 256>>>(h, h16, y16, ln1_g + (size_t)l * DD, ln1_b + (size_t)l * DD);
        // t = relu(h @ lin1 + b) -> fp16
        gemm_mma<1, 1><<<dim3(FFD / 128, NTOK / 128), 256, GEMM_SMEM>>>(h16, 512, wT16 + WT_LIN1(l), l1b, ff16, FFD);
        // y = t @ lin2 + b -> fp16
        gemm_mma<0, 1><<<dim3(DD / 128, NTOK / 128), 256, GEMM_SMEM>>>(ff16, 512, wT16 + WT_LIN2(l), l2b, y16, DD);
        // h = LN(h + y)
        add_ln_kernel<<<NTOK / 8, 256>>>(h, h16, y16, ln2_g + (size_t)l * DD, ln2_b + (size_t)l * DD);
    }

    // ov = cls @ fc_w + fc_b  (cls rows are h16[n*9,:], so lda = 9*512) -> fp32
    gemm_mma<0, 0><<<dim3(OUTD / 128, NSEQ / 128), 256, GEMM_SMEM>>>(h16, SS * DD, wT16 + WT_FC, fc_b, ov, OUTD);

    // out = raw * (1 + relu(ov))
    final_kernel<<<(NSEQ * OUTD / 4) / 256, 256>>>(raw, ov, out);
}

// round 17
// speedup vs baseline: 4.8131x; 1.0983x over previous
#include <cuda_runtime.h>
#include <cuda_fp16.h>
#include <cstdint>

// ---------------- problem constants ----------------
#define BB   32
#define TT   256
#define SS   9
#define EE   631
#define DD   512
#define FFD  512
#define HH   8
#define HDD  64
#define LL   2
#define OUTD 512
#define NSEQ (BB*TT)          // 8192 sequences
#define NTOK (NSEQ*SS)        // 73728 tokens
#define EPS  1e-5f

// ---------------- scratch (static device globals; no allocs) ----------------
__device__ float  g_h[(size_t)NTOK * DD];          // hidden state fp32
__device__ __half g_h16[(size_t)NTOK * DD];        // fp16 shadow of h
__device__ __half g_qkv16[(size_t)NTOK * 3 * DD];  // qkv (fp16)
__device__ __half g_ctx16[(size_t)NTOK * DD];      // attention ctx (fp16)
__device__ __half g_ff16[(size_t)NTOK * DD];       // relu(lin1) (fp16)
__device__ __half g_y16[(size_t)NTOK * DD];        // sublayer output y (fp16)
__device__ float  g_raw[(size_t)NSEQ * OUTD];      // raw_emb
__device__ __half g_wT16[3407872];                 // transposed weights [N,K] fp16

// weight-transpose offsets (elements)
#define WT_QKV(l)  ((size_t)(l) * 786432)
#define WT_OUT(l)  (1572864 + (size_t)(l) * 262144)
#define WT_LIN1(l) (2097152 + (size_t)(l) * 262144)
#define WT_LIN2(l) (2621440 + (size_t)(l) * 262144)
#define WT_FC      (3145728)

// ---------------- PTX helpers (target-neutral, sm_80-era) ----------------
__device__ __forceinline__ unsigned smem_u32(const void* p) {
    unsigned a;
    asm("{ .reg .u64 t; cvta.to.shared.u64 t, %1; cvt.u32.u64 %0, t; }" : "=r"(a) : "l"(p));
    return a;
}
__device__ __forceinline__ void cp16(unsigned dst, const void* src) {
    asm volatile("cp.async.cg.shared.global [%0], [%1], 16;" :: "r"(dst), "l"(src) : "memory");
}
__device__ __forceinline__ void ldmx4(unsigned addr, unsigned &r0, unsigned &r1,
                                      unsigned &r2, unsigned &r3) {
    asm volatile("ldmatrix.sync.aligned.m8n8.x4.shared.b16 {%0,%1,%2,%3}, [%4];"
                 : "=r"(r0), "=r"(r1), "=r"(r2), "=r"(r3) : "r"(addr));
}
__device__ __forceinline__ void mma_f16(float& d0, float& d1, float& d2, float& d3,
                                        unsigned a0, unsigned a1, unsigned a2, unsigned a3,
                                        unsigned b0, unsigned b1) {
    asm volatile("mma.sync.aligned.m16n8k16.row.col.f32.f16.f16.f32 "
                 "{%0,%1,%2,%3}, {%4,%5,%6,%7}, {%8,%9}, {%0,%1,%2,%3};"
                 : "+f"(d0), "+f"(d1), "+f"(d2), "+f"(d3)
                 : "r"(a0), "r"(a1), "r"(a2), "r"(a3), "r"(b0), "r"(b1));
}

// ---------------- fp16 mma GEMM ----------------
// C[M,N] = act(A[M,K=512] @ BT[N,K=512]^T + bias)
// BM=128 BN=128 BK=64, 256 threads (8 warps, 4x2, warp tile 32x64),
// 3-stage cp.async pipeline (8 mainloop iterations), 144B-padded SMEM rows,
// 2 CTAs/SM. cp.async issue placed after first ks-slice to avoid the
// post-barrier LSU convoy.
#define ST_A_BYTES (128 * 144)           // 18432
#define ST_BYTES   (2 * ST_A_BYTES)      // 36864 per stage
#define GEMM_SMEM  (3 * ST_BYTES)        // 110592

__device__ __forceinline__ void gemm_issue(unsigned st,
                                           const __half* __restrict__ A0, int lda,
                                           const __half* __restrict__ B0, int k0)
{
    const int tid = threadIdx.x;
#pragma unroll
    for (int i = 0; i < 4; i++) {
        int c = tid + i * 256;
        int row = c >> 3, seg = c & 7;
        cp16(st + row * 144 + seg * 16,              A0 + (size_t)row * lda + k0 + seg * 8);
        cp16(st + ST_A_BYTES + row * 144 + seg * 16, B0 + (size_t)row * 512 + k0 + seg * 8);
    }
    asm volatile("cp.async.commit_group;" ::: "memory");
}

// MODE: FINAL=1 -> fp32 out with out = raw*(1+relu(acc+bias))
template<int ACT, int OUT16, int FINAL>
__global__ __launch_bounds__(256, 2)
void gemm_mma(const __half* __restrict__ A, int lda,
              const __half* __restrict__ BT,
              const float* __restrict__ bias,
              const float* __restrict__ rawp,
              void* __restrict__ Cv, int ldc)
{
    extern __shared__ char smem[];
    const unsigned sbase = smem_u32(smem);
    const int tid = threadIdx.x, lid = tid & 31, wid = tid >> 5;
    const int wm = wid & 3, wn = wid >> 2;      // 4 x 2 warp grid
    const int bx = blockIdx.x, by = blockIdx.y;

    const __half* Ab = A  + (size_t)by * 128 * lda;
    const __half* Bb = BT + (size_t)bx * 128 * 512;

    gemm_issue(sbase,            Ab, lda, Bb, 0);
    gemm_issue(sbase + ST_BYTES, Ab, lda, Bb, 64);

    float c[2][8][4];
#pragma unroll
    for (int i = 0; i < 2; i++)
#pragma unroll
        for (int j = 0; j < 8; j++)
#pragma unroll
            for (int q = 0; q < 4; q++) c[i][j][q] = 0.f;

    // per-lane ldmatrix offsets
    const unsigned a_row = lid & 15, a_k = (lid >> 4) * 8;
    const unsigned b_n = (lid & 7) + ((lid >> 4) << 3), b_k = ((lid >> 3) & 1) * 8;

#pragma unroll 1
    for (int k = 0; k < 8; k++) {
        asm volatile("cp.async.wait_group 1;" ::: "memory");
        __syncthreads();

        const unsigned sA = sbase + (k % 3) * ST_BYTES;
        const unsigned sB = sA + ST_A_BYTES;
#pragma unroll
        for (int ks = 0; ks < 4; ks++) {
            unsigned a[2][4], b[4][4];
#pragma unroll
            for (int i = 0; i < 2; i++)
                ldmx4(sA + (wm * 32 + i * 16 + a_row) * 144 + (ks * 16 + a_k) * 2,
                      a[i][0], a[i][1], a[i][2], a[i][3]);
#pragma unroll
            for (int jj = 0; jj < 4; jj++)
                ldmx4(sB + (wn * 64 + jj * 16 + b_n) * 144 + (ks * 16 + b_k) * 2,
                      b[jj][0], b[jj][1], b[jj][2], b[jj][3]);
#pragma unroll
            for (int i = 0; i < 2; i++)
#pragma unroll
                for (int j = 0; j < 8; j++)
                    mma_f16(c[i][j][0], c[i][j][1], c[i][j][2], c[i][j][3],
                            a[i][0], a[i][1], a[i][2], a[i][3],
                            b[j >> 1][(j & 1) * 2], b[j >> 1][(j & 1) * 2 + 1]);

            // issue next stage after the first ks-slice: off the post-barrier
            // LSU burst, still ~1 full iteration of prefetch distance.
            if (ks == 0) {
                if (k < 6) gemm_issue(sbase + ((k + 2) % 3) * ST_BYTES, Ab, lda, Bb, (k + 2) * 64);
                else       asm volatile("cp.async.commit_group;" ::: "memory");
            }
        }
    }

    // ---------------- epilogue ----------------
    const int qrow = lid >> 2, qcol = (lid & 3) * 2;
    const int gcol = bx * 128 + wn * 64 + qcol;
    float2 bv[8];
#pragma unroll
    for (int j = 0; j < 8; j++) bv[j] = *reinterpret_cast<const float2*>(bias + gcol + j * 8);

    const size_t rbase = (size_t)by * 128 + wm * 32 + qrow;
#pragma unroll
    for (int i = 0; i < 2; i++) {
#pragma unroll
        for (int hh = 0; hh < 2; hh++) {
            size_t row = rbase + i * 16 + hh * 8;
#pragma unroll
            for (int j = 0; j < 8; j++) {
                float x = c[i][j][hh * 2 + 0] + bv[j].x;
                float y = c[i][j][hh * 2 + 1] + bv[j].y;
                if (ACT) { x = fmaxf(x, 0.f); y = fmaxf(y, 0.f); }
                if (FINAL) {
                    float2 rv = *reinterpret_cast<const float2*>(rawp + row * (size_t)ldc + gcol + j * 8);
                    float2 o;
                    o.x = rv.x * (1.f + fmaxf(x, 0.f));
                    o.y = rv.y * (1.f + fmaxf(y, 0.f));
                    float* p = (float*)Cv + row * ldc + gcol + j * 8;
                    *reinterpret_cast<float2*>(p) = o;
                } else if (OUT16) {
                    __half* p = (__half*)Cv + row * ldc + gcol + j * 8;
                    *reinterpret_cast<__half2*>(p) = __floats2half2_rn(x, y);
                } else {
                    float* p = (float*)Cv + row * ldc + gcol + j * 8;
                    *reinterpret_cast<float2*>(p) = make_float2(x, y);
                }
            }
        }
    }
}

// ---------------- batched weight transpose+convert: in[K=512,N] fp32 -> out[N,K] fp16 ----------------
struct TJobs {
    const float* src[9];
    __half*      dst[9];
    int          N[9];
};

__global__ void transpose_all_kernel(TJobs j)
{
    __shared__ float t[32][33];
    const int job = blockIdx.z;
    const int N = j.N[job];
    const int n0 = blockIdx.x * 32, k0 = blockIdx.y * 32;
    if (n0 >= N) return;
    const float* in = j.src[job];
    __half* out = j.dst[job];
    int x = threadIdx.x, y = threadIdx.y;     // 32 x 8
#pragma unroll
    for (int i = 0; i < 32; i += 8)
        t[y + i][x] = in[(size_t)(k0 + y + i) * N + n0 + x];
    __syncthreads();
#pragma unroll
    for (int i = 0; i < 32; i += 8)
        out[(size_t)(n0 + y + i) * 512 + k0 + x] = __float2half_rn(t[x][y + i]);
}

// ---------------- embedding gather ----------------
__global__ void embed_kernel(const int* __restrict__ x,
                             const float* __restrict__ w,
                             const float* __restrict__ b,
                             float* __restrict__ h, __half* __restrict__ h16)
{
    int i = blockIdx.x, t = threadIdx.x;     // NTOK blocks x 128 threads
    int e = x[i];
    float4 wv = reinterpret_cast<const float4*>(w)[(size_t)e * 128 + t];
    float4 bv = reinterpret_cast<const float4*>(b)[t];
    float4 r = make_float4(wv.x + bv.x, wv.y + bv.y, wv.z + bv.z, wv.w + bv.w);
    reinterpret_cast<float4*>(h)[(size_t)i * 128 + t] = r;
    __half2* hp = reinterpret_cast<__half2*>(h16 + (size_t)i * 512 + t * 4);
    hp[0] = __floats2half2_rn(r.x, r.y);
    hp[1] = __floats2half2_rn(r.z, r.w);
}

// ---------------- raw_emb ----------------
__global__ void raw_kernel(const int* __restrict__ x,
                           const float* __restrict__ w2,
                           const float* __restrict__ b2,
                           float* __restrict__ raw)
{
    int n = blockIdx.x, t = threadIdx.x;
    __shared__ int xs[SS];
    if (t < SS) xs[t] = x[n * SS + t];
    __syncthreads();
    float4 acc = reinterpret_cast<const float4*>(b2)[t];
#pragma unroll
    for (int s = 0; s < SS; s++) {
        float4 v = reinterpret_cast<const float4*>(w2)[((size_t)s * EE + xs[s]) * 128 + t];
        acc.x += v.x; acc.y += v.y; acc.z += v.z; acc.w += v.w;
    }
    reinterpret_cast<float4*>(raw)[(size_t)n * 128 + t] = acc;
}

// ---------------- attention: one CTA per sequence, fp16 SMEM staging ----------------
#define ROWPH 520     // padded row stride in halves (1040B)
#define ATTN_SMEM (3 * SS * ROWPH * 2 + HH * SS * SS * 4)   // 28080 + 2592 = 30672

__global__ __launch_bounds__(256)
void attn_kernel(const __half* __restrict__ qkv16, __half* __restrict__ ctx16)
{
    extern __shared__ __half smh[];
    __half* sq = smh;
    __half* sk = sq + SS * ROWPH;
    __half* sv = sk + SS * ROWPH;
    float*  sc = reinterpret_cast<float*>(sv + SS * ROWPH);

    const int n = blockIdx.x, tid = threadIdx.x;

    // stage q/k/v as raw fp16 bits (pure uint4 copy, no conversion)
    const uint4* q16 = reinterpret_cast<const uint4*>(qkv16 + (size_t)n * SS * 1536);
    for (int u = tid; u < SS * 192; u += 256) {
        int s = u / 192, c8 = u % 192;
        uint4 v = q16[u];
        int col = c8 * 8;
        __half* dst;
        if (col < 512)       dst = sq + s * ROWPH + col;
        else if (col < 1024) dst = sk + s * ROWPH + (col - 512);
        else                 dst = sv + s * ROWPH + (col - 1024);
        *reinterpret_cast<uint4*>(dst) = v;
    }
    __syncthreads();

    // scores[h][i][j] = q_i,h . k_j,h / 8   (fp32 accumulation)
    for (int p = tid; p < HH * SS * SS; p += 256) {
        int h = p / (SS * SS), rem = p % (SS * SS), i = rem / SS, j = rem % SS;
        const __half2* qp = reinterpret_cast<const __half2*>(sq + i * ROWPH + h * HDD);
        const __half2* kp = reinterpret_cast<const __half2*>(sk + j * ROWPH + h * HDD);
        float dot = 0.f;
#pragma unroll
        for (int d = 0; d < HDD / 2; d++) {
            float2 a = __half22float2(qp[d]);
            float2 b = __half22float2(kp[d]);
            dot += a.x * b.x;
            dot += a.y * b.y;
        }
        sc[p] = dot * 0.125f;
    }
    __syncthreads();

    // softmax over j (72 rows of 9)
    if (tid < HH * SS) {
        float* row = sc + tid * SS;
        float m = row[0];
#pragma unroll
        for (int j = 1; j < SS; j++) m = fmaxf(m, row[j]);
        float s2 = 0.f;
#pragma unroll
        for (int j = 0; j < SS; j++) { float e = __expf(row[j] - m); row[j] = e; s2 += e; }
        float inv = 1.f / s2;
#pragma unroll
        for (int j = 0; j < SS; j++) row[j] *= inv;
    }
    __syncthreads();

    // ctx[i][h*64+d] = sum_j attn[h][i][j] * v[j][h*64+d]
    __half* c16 = ctx16 + (size_t)n * SS * DD;
    for (int u = tid; u < SS * 128; u += 256) {
        int i = u >> 7, c4 = u & 127;
        int h = c4 >> 4;
        const float* arow = sc + (h * SS + i) * SS;
        float4 acc = make_float4(0.f, 0.f, 0.f, 0.f);
#pragma unroll
        for (int j = 0; j < SS; j++) {
            float a = arow[j];
            const __half2* vp = reinterpret_cast<const __half2*>(sv + j * ROWPH + c4 * 4);
            float2 v0 = __half22float2(vp[0]);
            float2 v1 = __half22float2(vp[1]);
            acc.x += a * v0.x; acc.y += a * v0.y; acc.z += a * v1.x; acc.w += a * v1.y;
        }
        __half2* cp2 = reinterpret_cast<__half2*>(c16 + i * 512 + c4 * 4);
        cp2[0] = __floats2half2_rn(acc.x, acc.y);
        cp2[1] = __floats2half2_rn(acc.z, acc.w);
    }
}

// ---------------- fused residual + layernorm (+ fp16 shadow) ----------------
__global__ __launch_bounds__(256)
void add_ln_kernel(float* __restrict__ h, __half* __restrict__ h16,
                   const __half* __restrict__ y16,
                   const float* __restrict__ gamma, const float* __restrict__ beta)
{
    int warp = threadIdx.x >> 5, lane = threadIdx.x & 31;
    size_t row = (size_t)blockIdx.x * 8 + warp;
    float4* h4        = reinterpret_cast<float4*>(h) + row * 128;
    const __half2* y2 = reinterpret_cast<const __half2*>(y16) + row * 256;

    float4 xv[4];
    float sum = 0.f, sq = 0.f;
#pragma unroll
    for (int q = 0; q < 4; q++) {
        float4 a = h4[q * 32 + lane];
        __half2 ya = y2[(q * 32 + lane) * 2], yb = y2[(q * 32 + lane) * 2 + 1];
        float2 fa = __half22float2(ya), fb = __half22float2(yb);
        float4 v = make_float4(a.x + fa.x, a.y + fa.y, a.z + fb.x, a.w + fb.y);
        xv[q] = v;
        sum += v.x + v.y + v.z + v.w;
        sq  += v.x * v.x + v.y * v.y + v.z * v.z + v.w * v.w;
    }
#pragma unroll
    for (int o = 16; o > 0; o >>= 1) {
        sum += __shfl_xor_sync(0xffffffffu, sum, o);
        sq  += __shfl_xor_sync(0xffffffffu, sq,  o);
    }
    float mean = sum * (1.f / 512.f);
    float var  = sq * (1.f / 512.f) - mean * mean;
    float rstd = rsqrtf(var + EPS);

    const float4* g4 = reinterpret_cast<const float4*>(gamma);
    const float4* b4 = reinterpret_cast<const float4*>(beta);
    __half2* hp = reinterpret_cast<__half2*>(h16) + row * 256;
#pragma unroll
    for (int q = 0; q < 4; q++) {
        float4 g = g4[q * 32 + lane], bb = b4[q * 32 + lane], v = xv[q];
        float4 o;
        o.x = (v.x - mean) * rstd * g.x + bb.x;
        o.y = (v.y - mean) * rstd * g.y + bb.y;
        o.z = (v.z - mean) * rstd * g.z + bb.z;
        o.w = (v.w - mean) * rstd * g.w + bb.w;
        h4[q * 32 + lane] = o;
        hp[(q * 32 + lane) * 2]     = __floats2half2_rn(o.x, o.y);
        hp[(q * 32 + lane) * 2 + 1] = __floats2half2_rn(o.z, o.w);
    }
}

// ---------------- launch ----------------
extern "C" void kernel_launch(void* const* d_in, const int* in_sizes, int n_in,
                              void* d_out, int out_size)
{
    const int*   x        = (const int*)  d_in[0];
    const float* adapt2_w = (const float*)d_in[1];
    const float* adapt2_b = (const float*)d_in[2];
    const float* adapt_w  = (const float*)d_in[3];
    const float* adapt_b  = (const float*)d_in[4];
    const float* qkv_w    = (const float*)d_in[5];
    const float* qkv_b    = (const float*)d_in[6];
    const float* out_w    = (const float*)d_in[7];
    const float* out_b    = (const float*)d_in[8];
    const float* ln1_g    = (const float*)d_in[9];
    const float* ln1_b    = (const float*)d_in[10];
    const float* lin1_w   = (const float*)d_in[11];
    const float* lin1_b   = (const float*)d_in[12];
    const float* lin2_w   = (const float*)d_in[13];
    const float* lin2_b   = (const float*)d_in[14];
    const float* ln2_g    = (const float*)d_in[15];
    const float* ln2_b    = (const float*)d_in[16];
    const float* fc_w     = (const float*)d_in[17];
    const float* fc_b     = (const float*)d_in[18];
    float* out = (float*)d_out;

    float  *h, *raw;
    __half *h16, *qkv16, *ctx16, *ff16, *y16, *wT16;
    cudaGetSymbolAddress((void**)&h,     g_h);
    cudaGetSymbolAddress((void**)&h16,   g_h16);
    cudaGetSymbolAddress((void**)&qkv16, g_qkv16);
    cudaGetSymbolAddress((void**)&ctx16, g_ctx16);
    cudaGetSymbolAddress((void**)&ff16,  g_ff16);
    cudaGetSymbolAddress((void**)&y16,   g_y16);
    cudaGetSymbolAddress((void**)&raw,   g_raw);
    cudaGetSymbolAddress((void**)&wT16,  g_wT16);

    cudaFuncSetAttribute(attn_kernel,       cudaFuncAttributeMaxDynamicSharedMemorySize, ATTN_SMEM);
    cudaFuncSetAttribute(gemm_mma<0, 1, 0>, cudaFuncAttributeMaxDynamicSharedMemorySize, GEMM_SMEM);
    cudaFuncSetAttribute(gemm_mma<1, 1, 0>, cudaFuncAttributeMaxDynamicSharedMemorySize, GEMM_SMEM);
    cudaFuncSetAttribute(gemm_mma<0, 0, 1>, cudaFuncAttributeMaxDynamicSharedMemorySize, GEMM_SMEM);

    // one batched transpose+convert launch for all 9 weight matrices
    TJobs tj;
    tj.src[0] = qkv_w;                          tj.dst[0] = wT16 + WT_QKV(0);  tj.N[0] = 1536;
    tj.src[1] = qkv_w + (size_t)DD * 3 * DD;    tj.dst[1] = wT16 + WT_QKV(1);  tj.N[1] = 1536;
    tj.src[2] = out_w;                          tj.dst[2] = wT16 + WT_OUT(0);  tj.N[2] = 512;
    tj.src[3] = out_w + (size_t)DD * DD;        tj.dst[3] = wT16 + WT_OUT(1);  tj.N[3] = 512;
    tj.src[4] = lin1_w;                         tj.dst[4] = wT16 + WT_LIN1(0); tj.N[4] = 512;
    tj.src[5] = lin1_w + (size_t)DD * FFD;      tj.dst[5] = wT16 + WT_LIN1(1); tj.N[5] = 512;
    tj.src[6] = lin2_w;                         tj.dst[6] = wT16 + WT_LIN2(0); tj.N[6] = 512;
    tj.src[7] = lin2_w + (size_t)FFD * DD;      tj.dst[7] = wT16 + WT_LIN2(1); tj.N[7] = 512;
    tj.src[8] = fc_w;                           tj.dst[8] = wT16 + WT_FC;      tj.N[8] = 512;
    transpose_all_kernel<<<dim3(1536 / 32, 512 / 32, 9), dim3(32, 8)>>>(tj);

    embed_kernel<<<NTOK, 128>>>(x, adapt_w, adapt_b, h, h16);
    raw_kernel<<<NSEQ, 128>>>(x, adapt2_w, adapt2_b, raw);

    for (int l = 0; l < LL; l++) {
        const float* qb  = qkv_b  + (size_t)l * 3 * DD;
        const float* ob  = out_b  + (size_t)l * DD;
        const float* l1b = lin1_b + (size_t)l * FFD;
        const float* l2b = lin2_b + (size_t)l * DD;

        // qkv = h @ qkv_w + b   -> fp16 (73728 x 1536)
        gemm_mma<0, 1, 0><<<dim3(1536 / 128, NTOK / 128), 256, GEMM_SMEM>>>(h16, 512, wT16 + WT_QKV(l), qb, nullptr, qkv16, 3 * DD);
        // ctx (fp16)
        attn_kernel<<<NSEQ, 256, ATTN_SMEM>>>(qkv16, ctx16);
        // y = ctx @ out_w + b   -> fp16
        gemm_mma<0, 1, 0><<<dim3(DD / 128, NTOK / 128), 256, GEMM_SMEM>>>(ctx16, 512, wT16 + WT_OUT(l), ob, nullptr, y16, DD);
        // h = LN(h + y)
        add_ln_kernel<<<NTOK / 8, 256>>>(h, h16, y16, ln1_g + (size_t)l * DD, ln1_b + (size_t)l * DD);
        // t = relu(h @ lin1 + b) -> fp16
        gemm_mma<1, 1, 0><<<dim3(FFD / 128, NTOK / 128), 256, GEMM_SMEM>>>(h16, 512, wT16 + WT_LIN1(l), l1b, nullptr, ff16, FFD);
        // y = t @ lin2 + b -> fp16
        gemm_mma<0, 1, 0><<<dim3(DD / 128, NTOK / 128), 256, GEMM_SMEM>>>(ff16, 512, wT16 + WT_LIN2(l), l2b, nullptr, y16, DD);
        // h = LN(h + y)
        add_ln_kernel<<<NTOK / 8, 256>>>(h, h16, y16, ln2_g + (size_t)l * DD, ln2_b + (size_t)l * DD);
    }

    // out = raw * (1 + relu(cls @ fc_w + fc_b))  — fused fc GEMM + final
    gemm_mma<0, 0, 1><<<dim3(OUTD / 128, NSEQ / 128), 256, GEMM_SMEM>>>(h16, SS * DD, wT16 + WT_FC, fc_b, raw, out, OUTD);
}